// round 4
// baseline (speedup 1.0000x reference)
#include <cuda_runtime.h>
#include <cuda_bf16.h>
#include <math.h>
#include <stdint.h>

#define BB   16384
#define DD   1024
#define PP   1024
#define OUTC 25
#define NTIL 8
#define MARGIN 0.05f
#define NSTAGE 3
#define STAGE_BYTES 32768            // 4 tiles * 8KB (Ahi, Alo, Bhi, Blo)
#define SM_EXTRA (NSTAGE * STAGE_BYTES)   // 98304: lam/idx region
#define SM_TOTAL (SM_EXTRA + 1024)

// ---------------- device scratch ----------------
__device__ float g_psq[PP];
__device__ float g_v1[PP];
__device__ float g_v2[PP];
__device__ float g_PW[PP * DD];
__device__ int   g_labels[BB];
__device__ float g_lam[BB];
__device__ float g_logits[(size_t)BB * PP];
__device__ float4 g_top2[(size_t)BB * NTIL];

__device__ __nv_bfloat16 g_pr_hi[(size_t)PP * DD];
__device__ __nv_bfloat16 g_pr_lo[(size_t)PP * DD];
__device__ __nv_bfloat16 g_fc_hi[(size_t)PP * DD];
__device__ __nv_bfloat16 g_fc_lo[(size_t)PP * DD];
__device__ __nv_bfloat16 g_wt_hi[(size_t)DD * DD];
__device__ __nv_bfloat16 g_wt_lo[(size_t)DD * DD];

// ---------------- helpers ----------------
__device__ __forceinline__ uint32_t smem_u32(const void* p) {
    uint32_t a;
    asm("{ .reg .u64 t; cvta.to.shared.u64 t, %1; cvt.u32.u64 %0, t; }" : "=r"(a) : "l"(p));
    return a;
}
__device__ __forceinline__ void ldsm4(uint32_t r[4], uint32_t addr) {
    asm volatile("ldmatrix.sync.aligned.m8n8.x4.shared.b16 {%0,%1,%2,%3}, [%4];"
                 : "=r"(r[0]), "=r"(r[1]), "=r"(r[2]), "=r"(r[3]) : "r"(addr));
}
__device__ __forceinline__ void mma16816(float c[4], const uint32_t a[4],
                                         uint32_t b0, uint32_t b1) {
    asm volatile("mma.sync.aligned.m16n8k16.row.col.f32.bf16.bf16.f32 "
                 "{%0,%1,%2,%3}, {%4,%5,%6,%7}, {%8,%9}, {%0,%1,%2,%3};"
                 : "+f"(c[0]), "+f"(c[1]), "+f"(c[2]), "+f"(c[3])
                 : "r"(a[0]), "r"(a[1]), "r"(a[2]), "r"(a[3]), "r"(b0), "r"(b1));
}
__device__ __forceinline__ uint32_t pk2(float a, float b) {
    __nv_bfloat162 t;
    t.x = __float2bfloat16(a); t.y = __float2bfloat16(b);
    return *reinterpret_cast<uint32_t*>(&t);
}
__device__ __forceinline__ void top2_upd(float s, int idx, float& v1, int& i1,
                                         float& v2, int& i2) {
    if (s < v1 || (s == v1 && idx < i1)) { v2 = v1; i2 = i1; v1 = s; i1 = idx; }
    else if (s < v2 || (s == v2 && idx < i2)) { v2 = s; i2 = idx; }
}
__device__ __forceinline__ void top2_merge(float w1, int j1, float w2, int j2,
                                           float& v1, int& i1, float& v2, int& i2) {
    top2_upd(w1, j1, v1, i1, v2, i2);
    top2_upd(w2, j2, v1, i1, v2, i2);
}

// =================================================================
// prep: p_sq, v1, v2
// =================================================================
__global__ __launch_bounds__(256) void prep_kernel(
    const float* __restrict__ protos, const float* __restrict__ lin_w)
{
    int p = blockIdx.x, t = threadIdx.x;
    float sq = 0.f, a1 = 0.f, a2 = 0.f;
    const float* row = protos + (size_t)p * DD;
    for (int k = t; k < DD; k += 256) {
        float v = row[k];
        sq = fmaf(v, v, sq);
        a1 = fmaf(v, lin_w[k], a1);
        a2 = fmaf(v, lin_w[DD + k], a2);
    }
    __shared__ float s1[256], s2[256], s3[256];
    s1[t] = sq; s2[t] = a1; s3[t] = a2;
    __syncthreads();
    for (int off = 128; off; off >>= 1) {
        if (t < off) { s1[t] += s1[t+off]; s2[t] += s2[t+off]; s3[t] += s3[t+off]; }
        __syncthreads();
    }
    if (t == 0) { g_psq[p] = s1[0]; g_v1[p] = s2[0]; g_v2[p] = s3[0]; }
}

// =================================================================
// split fp32 -> bf16 hi + lo (row-major preserved)
// =================================================================
__global__ __launch_bounds__(256) void split_kernel(
    const float* __restrict__ src, __nv_bfloat16* __restrict__ hi,
    __nv_bfloat16* __restrict__ lo, int n4)
{
    int i = blockIdx.x * 256 + threadIdx.x;
    if (i >= n4) return;
    float4 v = reinterpret_cast<const float4*>(src)[i];
    uint32_t h0 = pk2(v.x, v.y), h1 = pk2(v.z, v.w);
    __nv_bfloat162* hv = reinterpret_cast<__nv_bfloat162*>(&h0);
    __nv_bfloat162* hv1 = reinterpret_cast<__nv_bfloat162*>(&h1);
    uint32_t l0 = pk2(v.x - __bfloat162float(hv->x),  v.y - __bfloat162float(hv->y));
    uint32_t l1 = pk2(v.z - __bfloat162float(hv1->x), v.w - __bfloat162float(hv1->y));
    reinterpret_cast<uint32_t*>(hi)[2*i]   = h0;
    reinterpret_cast<uint32_t*>(hi)[2*i+1] = h1;
    reinterpret_cast<uint32_t*>(lo)[2*i]   = l0;
    reinterpret_cast<uint32_t*>(lo)[2*i+1] = l1;
}

// =================================================================
// transpose + split: WT[n][k] = W[k][n], bf16 hi/lo
// =================================================================
__global__ __launch_bounds__(256) void splitT_kernel(
    const float* __restrict__ W, __nv_bfloat16* __restrict__ hiT,
    __nv_bfloat16* __restrict__ loT)
{
    __shared__ float tile[32][33];
    int n0 = blockIdx.x * 32, k0 = blockIdx.y * 32;
    int tx = threadIdx.x & 31, ty = threadIdx.x >> 5;   // 8 rows per pass
#pragma unroll
    for (int i = 0; i < 4; i++) {
        int kk = ty + i * 8;
        tile[kk][tx] = W[(size_t)(k0 + kk) * DD + n0 + tx];
    }
    __syncthreads();
#pragma unroll
    for (int i = 0; i < 4; i++) {
        int a = ty + i * 8;                 // n-local
        float v = tile[tx][a];              // W[k0+tx][n0+a]
        __nv_bfloat16 h = __float2bfloat16(v);
        hiT[(size_t)(n0 + a) * DD + k0 + tx] = h;
        loT[(size_t)(n0 + a) * DD + k0 + tx] = __float2bfloat16(v - __bfloat162float(h));
    }
}

// =================================================================
// HMMA split-bf16 GEMM, 128x128 tile, BK=32, 3-stage pipeline.
// AMODE 0: A pre-split bf16 (cp.async)   [PW]
// AMODE 1: A fp32, split on the fly      [dist]
// AMODE 2: A fp32 mixup (gather+blend+split) [logits]
// MODE 0: top2(psq - 2*dot) -> g_top2
// MODE 1: +bias, leaky -> outp stride PP
// MODE 2: plain store  -> outp stride DD
// =================================================================
template <int AMODE, int MODE>
__global__ __launch_bounds__(256)
void hmma_gemm_kernel(const __nv_bfloat16* __restrict__ Ahi, const __nv_bfloat16* __restrict__ Alo,
                      const float* __restrict__ A32, const int* __restrict__ idxp,
                      const __nv_bfloat16* __restrict__ Bhi, const __nv_bfloat16* __restrict__ Blo,
                      const float* __restrict__ bias, float* __restrict__ outp)
{
    extern __shared__ char smem[];
    const uint32_t sb = smem_u32(smem);
    const int tid = threadIdx.x;
    const int lane = tid & 31;
    const int w = tid >> 5;
    const int wm = w & 3;
    const int wn = w >> 2;
    const int row0 = blockIdx.y * 128;
    const int col0 = blockIdx.x * 128;

    float* lam_s = reinterpret_cast<float*>(smem + SM_EXTRA);
    int*   idx_s = reinterpret_cast<int*>(smem + SM_EXTRA + 512);
    if (AMODE == 2) {
        if (tid < 128) {
            lam_s[tid] = g_lam[row0 + tid];
            idx_s[tid] = idxp[row0 + tid];
        }
        __syncthreads();
    }

    const int q  = lane >> 3;
    const int lr = lane & 7;
    const int achk = q >> 1;
    const int bchk = q & 1;
    int arow[2], brow[4];
#pragma unroll
    for (int mi = 0; mi < 2; mi++) arow[mi] = wm*32 + mi*16 + ((q & 1) << 3) + lr;
#pragma unroll
    for (int ng = 0; ng < 4; ng++) brow[ng] = wn*64 + ng*16 + ((q >> 1) << 3) + lr;

    float c[2][8][4];
#pragma unroll
    for (int mi = 0; mi < 2; mi++)
#pragma unroll
        for (int nf = 0; nf < 8; nf++)
#pragma unroll
            for (int j = 0; j < 4; j++) c[mi][nf][j] = 0.f;

    float4 va[2][2];   // A fp32 staging (AMODE 1/2)

    // --- B tiles (and A tiles for AMODE 0) via cp.async ---
    auto issueB = [&](int st, int kt) {
        const int k0 = kt << 5;
        const uint32_t sbase = sb + st * STAGE_BYTES;
        if (AMODE == 0) {
#pragma unroll
            for (int it = 0; it < 8; it++) {
                int ch = it * 256 + tid;
                int t = ch >> 9;
                int within = ch & 511;
                int r = within >> 2, cc = within & 3;
                const __nv_bfloat16* src = (t == 0) ? Ahi : (t == 1) ? Alo : (t == 2) ? Bhi : Blo;
                int rbase = (t < 2) ? row0 : col0;
                const void* g = src + (size_t)(rbase + r) * DD + k0 + cc * 8;
                uint32_t s = sbase + t * 8192 + r * 64 + ((cc ^ ((r >> 1) & 3)) << 4);
                asm volatile("cp.async.cg.shared.global [%0], [%1], 16;" :: "r"(s), "l"(g));
            }
        } else {
#pragma unroll
            for (int it = 0; it < 4; it++) {
                int ch = it * 256 + tid;
                int t = ch >> 9;                    // 0 = Bhi, 1 = Blo
                int within = ch & 511;
                int r = within >> 2, cc = within & 3;
                const __nv_bfloat16* src = t ? Blo : Bhi;
                const void* g = src + (size_t)(col0 + r) * DD + k0 + cc * 8;
                uint32_t s = sbase + (2 + t) * 8192 + r * 64 + ((cc ^ ((r >> 1) & 3)) << 4);
                asm volatile("cp.async.cg.shared.global [%0], [%1], 16;" :: "r"(s), "l"(g));
            }
        }
        asm volatile("cp.async.commit_group;" ::: "memory");
    };

    // --- A fp32 load (+optional mixup blend) into registers ---
    auto ldgA = [&](int kt) {
        const int k0 = kt << 5;
#pragma unroll
        for (int it = 0; it < 2; it++) {
            int ch = it * 256 + tid;
            int r = ch >> 2, cc = ch & 3;
            const float* g = A32 + (size_t)(row0 + r) * DD + k0 + cc * 8;
            float4 x0 = *reinterpret_cast<const float4*>(g);
            float4 x1 = *reinterpret_cast<const float4*>(g + 4);
            if (AMODE == 2) {
                float lamv = lam_s[r];
                float om = 1.f - lamv;
                const float* gp = A32 + (size_t)idx_s[r] * DD + k0 + cc * 8;
                float4 y0 = *reinterpret_cast<const float4*>(gp);
                float4 y1 = *reinterpret_cast<const float4*>(gp + 4);
                x0.x = fmaf(lamv, x0.x, om * y0.x); x0.y = fmaf(lamv, x0.y, om * y0.y);
                x0.z = fmaf(lamv, x0.z, om * y0.z); x0.w = fmaf(lamv, x0.w, om * y0.w);
                x1.x = fmaf(lamv, x1.x, om * y1.x); x1.y = fmaf(lamv, x1.y, om * y1.y);
                x1.z = fmaf(lamv, x1.z, om * y1.z); x1.w = fmaf(lamv, x1.w, om * y1.w);
            }
            va[it][0] = x0; va[it][1] = x1;
        }
    };

    // --- convert staged A to bf16 hi/lo and store to stage smem ---
    auto stsA = [&](int st) {
        const uint32_t sbase = sb + st * STAGE_BYTES;
#pragma unroll
        for (int it = 0; it < 2; it++) {
            int ch = it * 256 + tid;
            int r = ch >> 2, cc = ch & 3;
            float f[8] = { va[it][0].x, va[it][0].y, va[it][0].z, va[it][0].w,
                           va[it][1].x, va[it][1].y, va[it][1].z, va[it][1].w };
            uint32_t h[4], l[4];
#pragma unroll
            for (int j = 0; j < 4; j++) {
                h[j] = pk2(f[2*j], f[2*j+1]);
                __nv_bfloat162* hv = reinterpret_cast<__nv_bfloat162*>(&h[j]);
                l[j] = pk2(f[2*j]   - __bfloat162float(hv->x),
                           f[2*j+1] - __bfloat162float(hv->y));
            }
            uint32_t addr = sbase + r * 64 + ((cc ^ ((r >> 1) & 3)) << 4);
            asm volatile("st.shared.v4.b32 [%0], {%1,%2,%3,%4};"
                         :: "r"(addr), "r"(h[0]), "r"(h[1]), "r"(h[2]), "r"(h[3]));
            asm volatile("st.shared.v4.b32 [%0], {%1,%2,%3,%4};"
                         :: "r"(addr + 8192), "r"(l[0]), "r"(l[1]), "r"(l[2]), "r"(l[3]));
        }
    };

    auto compute = [&](int st) {
        const uint32_t sbase = sb + st * STAGE_BYTES;
#pragma unroll
        for (int ks = 0; ks < 2; ks++) {
            uint32_t ah[2][4], al[2][4], bh[4][4], bl[4][4];
#pragma unroll
            for (int mi = 0; mi < 2; mi++) {
                uint32_t ra = sbase + arow[mi] * 64 +
                              ((((ks << 1) | achk) ^ ((arow[mi] >> 1) & 3)) << 4);
                ldsm4(ah[mi], ra);
                ldsm4(al[mi], ra + 8192);
            }
#pragma unroll
            for (int ng = 0; ng < 4; ng++) {
                uint32_t rb = sbase + 2 * 8192 + brow[ng] * 64 +
                              ((((ks << 1) | bchk) ^ ((brow[ng] >> 1) & 3)) << 4);
                ldsm4(bh[ng], rb);
                ldsm4(bl[ng], rb + 8192);
            }
#pragma unroll
            for (int mi = 0; mi < 2; mi++)
#pragma unroll
                for (int ng = 0; ng < 4; ng++)
#pragma unroll
                    for (int h = 0; h < 2; h++) {
                        int nf = ng * 2 + h;
                        mma16816(c[mi][nf], ah[mi], bh[ng][h*2], bh[ng][h*2+1]);
                        mma16816(c[mi][nf], ah[mi], bl[ng][h*2], bl[ng][h*2+1]);
                        mma16816(c[mi][nf], al[mi], bh[ng][h*2], bh[ng][h*2+1]);
                    }
        }
    };

    const int NK = DD / 32;
    if (AMODE == 0) {
        issueB(0, 0);
        issueB(1, 1);
    } else {
        ldgA(0); stsA(0);
        issueB(0, 0);
        issueB(1, 1);
        ldgA(1);
    }
    for (int kt = 0; kt < NK; kt++) {
        if (kt == NK - 1) asm volatile("cp.async.wait_group 0;" ::: "memory");
        else              asm volatile("cp.async.wait_group 1;" ::: "memory");
        __syncthreads();
        compute(kt % NSTAGE);
        if (AMODE == 0) {
            if (kt + 2 < NK) issueB((kt + 2) % NSTAGE, kt + 2);
        } else {
            if (kt + 1 < NK) stsA((kt + 1) % NSTAGE);
            if (kt + 2 < NK) { ldgA(kt + 2); issueB((kt + 2) % NSTAGE, kt + 2); }
        }
        __syncthreads();
    }
    __syncthreads();   // stage region free for epilogue reuse

    if (MODE == 0) {
        float4* mbuf = reinterpret_cast<float4*>(smem);
#pragma unroll
        for (int mi = 0; mi < 2; mi++)
#pragma unroll
            for (int rh = 0; rh < 2; rh++) {
                int lrow_ = wm*32 + mi*16 + rh*8 + (lane >> 2);
                float v1 = 3.4e38f, v2 = 3.4e38f;
                int i1 = 0, i2 = 0;
#pragma unroll
                for (int nf = 0; nf < 8; nf++) {
                    int col = col0 + wn*64 + nf*8 + ((lane & 3) << 1);
                    float s0 = bias[col]     - 2.f * c[mi][nf][rh*2];
                    float s1 = bias[col + 1] - 2.f * c[mi][nf][rh*2+1];
                    top2_upd(s0, col,     v1, i1, v2, i2);
                    top2_upd(s1, col + 1, v1, i1, v2, i2);
                }
#pragma unroll
                for (int d = 1; d <= 2; d <<= 1) {
                    float w1 = __shfl_xor_sync(0xffffffffu, v1, d);
                    float w2 = __shfl_xor_sync(0xffffffffu, v2, d);
                    int   j1 = __shfl_xor_sync(0xffffffffu, i1, d);
                    int   j2 = __shfl_xor_sync(0xffffffffu, i2, d);
                    top2_merge(w1, j1, w2, j2, v1, i1, v2, i2);
                }
                if ((lane & 3) == 0)
                    mbuf[lrow_ * 2 + wn] =
                        make_float4(v1, __int_as_float(i1), v2, __int_as_float(i2));
            }
        __syncthreads();
        if (tid < 128) {
            float4 a = mbuf[tid * 2 + 0];
            float4 b = mbuf[tid * 2 + 1];
            float v1 = a.x, v2 = a.z;
            int i1 = __float_as_int(a.y), i2 = __float_as_int(a.w);
            top2_merge(b.x, __float_as_int(b.y), b.z, __float_as_int(b.w), v1, i1, v2, i2);
            reinterpret_cast<float4*>(outp)[(size_t)(row0 + tid) * NTIL + blockIdx.x] =
                make_float4(v1, __int_as_float(i1), v2, __int_as_float(i2));
        }
    } else {
        const int NSTRIDE = (MODE == 1) ? PP : DD;
#pragma unroll
        for (int mi = 0; mi < 2; mi++)
#pragma unroll
            for (int rh = 0; rh < 2; rh++) {
                int r = row0 + wm*32 + mi*16 + rh*8 + (lane >> 2);
#pragma unroll
                for (int nf = 0; nf < 8; nf++) {
                    int col = col0 + wn*64 + nf*8 + ((lane & 3) << 1);
                    float v0 = c[mi][nf][rh*2];
                    float v1 = c[mi][nf][rh*2+1];
                    if (MODE == 1) {
                        v0 += bias[col];
                        v1 += bias[col + 1];
                        v0 = v0 > 0.f ? v0 : 0.01f * v0;
                        v1 = v1 > 0.f ? v1 : 0.01f * v1;
                    }
                    float2 o = {v0, v1};
                    *reinterpret_cast<float2*>(&outp[(size_t)r * NSTRIDE + col]) = o;
                }
            }
    }
}

// =================================================================
// merge per-tile top2 + exact rescue for near-ties
// =================================================================
__global__ __launch_bounds__(256)
void argmin_reduce_kernel(const float* __restrict__ patient, const float* __restrict__ protos)
{
    int w = (blockIdx.x * 256 + threadIdx.x) >> 5;
    int lane = threadIdx.x & 31;
    if (w >= BB) return;
    float v1 = 0.f, v2 = 0.f; int i1 = 0, i2 = 0;
    if (lane == 0) {
        v1 = 3.4e38f; v2 = 3.4e38f;
        for (int t = 0; t < NTIL; t++) {
            float4 qd = g_top2[(size_t)w * NTIL + t];
            top2_merge(qd.x, __float_as_int(qd.y), qd.z, __float_as_int(qd.w), v1, i1, v2, i2);
        }
    }
    v1 = __shfl_sync(0xffffffffu, v1, 0);
    v2 = __shfl_sync(0xffffffffu, v2, 0);
    i1 = __shfl_sync(0xffffffffu, i1, 0);
    i2 = __shfl_sync(0xffffffffu, i2, 0);
    if (v2 - v1 >= MARGIN) {
        if (lane == 0) g_labels[w] = i1;
        return;
    }
    const float* x  = patient + (size_t)w * DD;
    const float* pA = protos + (size_t)i1 * DD;
    const float* pB = protos + (size_t)i2 * DD;
    double da = 0.0, db = 0.0;
    for (int k = lane; k < DD; k += 32) {
        double xv = x[k];
        da += xv * (double)pA[k];
        db += xv * (double)pB[k];
    }
#pragma unroll
    for (int off = 16; off; off >>= 1) {
        da += __shfl_down_sync(0xffffffffu, da, off);
        db += __shfl_down_sync(0xffffffffu, db, off);
    }
    if (lane == 0) {
        double sA = (double)g_psq[i1] - 2.0 * da;
        double sB = (double)g_psq[i2] - 2.0 * db;
        bool pickA = (sA < sB) || (sA == sB && i1 < i2);
        g_labels[w] = pickA ? i1 : i2;
    }
}

// =================================================================
// lam[b] = sigmoid(PW[la].protos[lb] + bil_b + v1[la] + v2[lb])
// =================================================================
__global__ __launch_bounds__(256)
void lam_kernel(const int* __restrict__ index, const float* __restrict__ bilinear_b,
                const float* __restrict__ protos)
{
    int w = (blockIdx.x * 256 + threadIdx.x) >> 5;
    int lane = threadIdx.x & 31;
    if (w >= BB) return;
    int la = g_labels[w];
    int lb = g_labels[index[w]];
    const float4* a = reinterpret_cast<const float4*>(g_PW + (size_t)la * DD);
    const float4* p = reinterpret_cast<const float4*>(protos + (size_t)lb * DD);
    float acc = 0.f;
    for (int k = lane; k < DD / 4; k += 32) {
        float4 u = a[k], v = p[k];
        acc = fmaf(u.x, v.x, acc); acc = fmaf(u.y, v.y, acc);
        acc = fmaf(u.z, v.z, acc); acc = fmaf(u.w, v.w, acc);
    }
#pragma unroll
    for (int off = 16; off; off >>= 1) acc += __shfl_down_sync(0xffffffffu, acc, off);
    if (lane == 0) {
        float s = acc + bilinear_b[0] + g_v1[la] + g_v2[lb];
        g_lam[w] = 1.f / (1.f + expf(-s));
    }
}

// =================================================================
// class head (warp per row)
// =================================================================
__global__ __launch_bounds__(256)
void class_kernel(const float* __restrict__ cw, const float* __restrict__ cb,
                  float* __restrict__ out)
{
    int gw = (blockIdx.x * 256 + threadIdx.x) >> 5;
    int lane = threadIdx.x & 31;
    if (gw >= BB) return;
    const float* lrow = g_logits + (size_t)gw * PP;
    float acc[OUTC];
#pragma unroll
    for (int o = 0; o < OUTC; o++) acc[o] = 0.f;
    for (int p = lane; p < PP; p += 32) {
        float v = lrow[p];
#pragma unroll
        for (int o = 0; o < OUTC; o++) acc[o] = fmaf(v, cw[o * PP + p], acc[o]);
    }
#pragma unroll
    for (int o = 0; o < OUTC; o++)
        for (int off = 16; off; off >>= 1)
            acc[o] += __shfl_down_sync(0xffffffffu, acc[o], off);
    if (lane == 0)
#pragma unroll
        for (int o = 0; o < OUTC; o++)
            out[(size_t)gw * OUTC + o] = acc[o] + cb[o];
}

// =================================================================
// launch
// =================================================================
extern "C" void kernel_launch(void* const* d_in, const int* in_sizes, int n_in,
                              void* d_out, int out_size)
{
    const float* patient    = (const float*)d_in[0];
    const float* protos     = (const float*)d_in[1];
    const int*   index      = (const int*)  d_in[2];
    const float* bilinear_w = (const float*)d_in[3];
    const float* bilinear_b = (const float*)d_in[4];
    const float* lin_w      = (const float*)d_in[5];
    const float* proto_fc_w = (const float*)d_in[6];
    const float* proto_fc_b = (const float*)d_in[7];
    const float* class_fc_w = (const float*)d_in[8];
    const float* class_fc_b = (const float*)d_in[9];
    float* out = (float*)d_out;

    float *pPW, *pPsq, *pLogits;
    float4* pTop2;
    __nv_bfloat16 *pPrHi, *pPrLo, *pFcHi, *pFcLo, *pWtHi, *pWtLo;
    cudaGetSymbolAddress((void**)&pPW, g_PW);
    cudaGetSymbolAddress((void**)&pPsq, g_psq);
    cudaGetSymbolAddress((void**)&pLogits, g_logits);
    cudaGetSymbolAddress((void**)&pTop2, g_top2);
    cudaGetSymbolAddress((void**)&pPrHi, g_pr_hi);
    cudaGetSymbolAddress((void**)&pPrLo, g_pr_lo);
    cudaGetSymbolAddress((void**)&pFcHi, g_fc_hi);
    cudaGetSymbolAddress((void**)&pFcLo, g_fc_lo);
    cudaGetSymbolAddress((void**)&pWtHi, g_wt_hi);
    cudaGetSymbolAddress((void**)&pWtLo, g_wt_lo);

    cudaFuncSetAttribute(hmma_gemm_kernel<0,2>, cudaFuncAttributeMaxDynamicSharedMemorySize, SM_TOTAL);
    cudaFuncSetAttribute(hmma_gemm_kernel<1,0>, cudaFuncAttributeMaxDynamicSharedMemorySize, SM_TOTAL);
    cudaFuncSetAttribute(hmma_gemm_kernel<2,1>, cudaFuncAttributeMaxDynamicSharedMemorySize, SM_TOTAL);

    prep_kernel<<<PP, 256>>>(protos, lin_w);

    split_kernel<<<(PP * DD / 4) / 256, 256>>>(protos, pPrHi, pPrLo, PP * DD / 4);
    split_kernel<<<(PP * DD / 4) / 256, 256>>>(proto_fc_w, pFcHi, pFcLo, PP * DD / 4);
    splitT_kernel<<<dim3(32, 32), 256>>>(bilinear_w, pWtHi, pWtLo);

    // PW = protos @ W (HMMA NT vs transposed-split W)
    hmma_gemm_kernel<0,2><<<dim3(DD / 128, PP / 128), 256, SM_TOTAL>>>(
        pPrHi, pPrLo, nullptr, nullptr, pWtHi, pWtLo, nullptr, pPW);

    // distance GEMM (A split in-kernel) + per-tile top2
    hmma_gemm_kernel<1,0><<<dim3(PP / 128, BB / 128), 256, SM_TOTAL>>>(
        nullptr, nullptr, patient, nullptr, pPrHi, pPrLo, pPsq, (float*)pTop2);

    argmin_reduce_kernel<<<BB / 8, 256>>>(patient, protos);

    lam_kernel<<<BB / 8, 256>>>(index, bilinear_b, protos);

    // logits GEMM (mixup fused into A load; +bias, leaky)
    hmma_gemm_kernel<2,1><<<dim3(PP / 128, BB / 128), 256, SM_TOTAL>>>(
        nullptr, nullptr, patient, index, pFcHi, pFcLo, proto_fc_b, pLogits);

    class_kernel<<<BB / 8, 256>>>(class_fc_w, class_fc_b, out);
}

// round 5
// speedup vs baseline: 1.5790x; 1.5790x over previous
#include <cuda_runtime.h>
#include <cuda_fp16.h>
#include <math.h>
#include <stdint.h>

#define BB   16384
#define DD   1024
#define PP   1024
#define OUTC 25
#define NTIL 8
#define MARGIN 0.10f
#define NSTAGE 3

// ---------------- device scratch ----------------
__device__ float g_psq[PP];
__device__ float g_v1[PP];
__device__ float g_v2[PP];
__device__ float g_PW[PP * DD];
__device__ int   g_labels[BB];
__device__ float g_lam[BB];
__device__ float g_logits[(size_t)BB * PP];
__device__ float4 g_top2[(size_t)BB * NTIL];

__device__ __half g_pa_hi[(size_t)BB * DD];
__device__ __half g_pa_lo[(size_t)BB * DD];
__device__ __half g_pr_hi[(size_t)PP * DD];
__device__ __half g_pr_lo[(size_t)PP * DD];
__device__ __half g_fc_hi[(size_t)PP * DD];
__device__ __half g_fc_lo[(size_t)PP * DD];
__device__ __half g_wt_hi[(size_t)DD * DD];
__device__ __half g_wt_lo[(size_t)DD * DD];
__device__ __half g_mx_hi[(size_t)BB * DD];
__device__ __half g_mx_lo[(size_t)BB * DD];

// ---------------- helpers ----------------
__device__ __forceinline__ uint32_t smem_u32(const void* p) {
    uint32_t a;
    asm("{ .reg .u64 t; cvta.to.shared.u64 t, %1; cvt.u32.u64 %0, t; }" : "=r"(a) : "l"(p));
    return a;
}
__device__ __forceinline__ void ldsm4(uint32_t r[4], uint32_t addr) {
    asm volatile("ldmatrix.sync.aligned.m8n8.x4.shared.b16 {%0,%1,%2,%3}, [%4];"
                 : "=r"(r[0]), "=r"(r[1]), "=r"(r[2]), "=r"(r[3]) : "r"(addr));
}
__device__ __forceinline__ void mma16816(float c[4], const uint32_t a[4],
                                         uint32_t b0, uint32_t b1) {
    asm volatile("mma.sync.aligned.m16n8k16.row.col.f32.f16.f16.f32 "
                 "{%0,%1,%2,%3}, {%4,%5,%6,%7}, {%8,%9}, {%0,%1,%2,%3};"
                 : "+f"(c[0]), "+f"(c[1]), "+f"(c[2]), "+f"(c[3])
                 : "r"(a[0]), "r"(a[1]), "r"(a[2]), "r"(a[3]), "r"(b0), "r"(b1));
}
__device__ __forceinline__ uint32_t pk2h(float a, float b) {
    __half2 t;
    t.x = __float2half(a); t.y = __float2half(b);
    return *reinterpret_cast<uint32_t*>(&t);
}
__device__ __forceinline__ void top2_upd(float s, int idx, float& v1, int& i1,
                                         float& v2, int& i2) {
    if (s < v1 || (s == v1 && idx < i1)) { v2 = v1; i2 = i1; v1 = s; i1 = idx; }
    else if (s < v2 || (s == v2 && idx < i2)) { v2 = s; i2 = idx; }
}
__device__ __forceinline__ void top2_merge(float w1, int j1, float w2, int j2,
                                           float& v1, int& i1, float& v2, int& i2) {
    top2_upd(w1, j1, v1, i1, v2, i2);
    top2_upd(w2, j2, v1, i1, v2, i2);
}

// =================================================================
// prep: p_sq, v1, v2
// =================================================================
__global__ __launch_bounds__(256) void prep_kernel(
    const float* __restrict__ protos, const float* __restrict__ lin_w)
{
    int p = blockIdx.x, t = threadIdx.x;
    float sq = 0.f, a1 = 0.f, a2 = 0.f;
    const float* row = protos + (size_t)p * DD;
    for (int k = t; k < DD; k += 256) {
        float v = row[k];
        sq = fmaf(v, v, sq);
        a1 = fmaf(v, lin_w[k], a1);
        a2 = fmaf(v, lin_w[DD + k], a2);
    }
    __shared__ float s1[256], s2[256], s3[256];
    s1[t] = sq; s2[t] = a1; s3[t] = a2;
    __syncthreads();
    for (int off = 128; off; off >>= 1) {
        if (t < off) { s1[t] += s1[t+off]; s2[t] += s2[t+off]; s3[t] += s3[t+off]; }
        __syncthreads();
    }
    if (t == 0) { g_psq[p] = s1[0]; g_v1[p] = s2[0]; g_v2[p] = s3[0]; }
}

// =================================================================
// split fp32 -> fp16 hi + lo
// =================================================================
__global__ __launch_bounds__(256) void split_kernel(
    const float* __restrict__ src, __half* __restrict__ hi,
    __half* __restrict__ lo, int n4)
{
    int i = blockIdx.x * 256 + threadIdx.x;
    if (i >= n4) return;
    float4 v = reinterpret_cast<const float4*>(src)[i];
    uint32_t h0 = pk2h(v.x, v.y), h1 = pk2h(v.z, v.w);
    __half2* hv0 = reinterpret_cast<__half2*>(&h0);
    __half2* hv1 = reinterpret_cast<__half2*>(&h1);
    uint32_t l0 = pk2h(v.x - __half2float(hv0->x), v.y - __half2float(hv0->y));
    uint32_t l1 = pk2h(v.z - __half2float(hv1->x), v.w - __half2float(hv1->y));
    reinterpret_cast<uint32_t*>(hi)[2*i]   = h0;
    reinterpret_cast<uint32_t*>(hi)[2*i+1] = h1;
    reinterpret_cast<uint32_t*>(lo)[2*i]   = l0;
    reinterpret_cast<uint32_t*>(lo)[2*i+1] = l1;
}

// =================================================================
// transpose + split: WT[n][k] = W[k][n], fp16 hi/lo
// =================================================================
__global__ __launch_bounds__(256) void splitT_kernel(
    const float* __restrict__ W, __half* __restrict__ hiT,
    __half* __restrict__ loT)
{
    __shared__ float tile[32][33];
    int n0 = blockIdx.x * 32, k0 = blockIdx.y * 32;
    int tx = threadIdx.x & 31, ty = threadIdx.x >> 5;
#pragma unroll
    for (int i = 0; i < 4; i++) {
        int kk = ty + i * 8;
        tile[kk][tx] = W[(size_t)(k0 + kk) * DD + n0 + tx];
    }
    __syncthreads();
#pragma unroll
    for (int i = 0; i < 4; i++) {
        int a = ty + i * 8;
        float v = tile[tx][a];
        __half h = __float2half(v);
        hiT[(size_t)(n0 + a) * DD + k0 + tx] = h;
        loT[(size_t)(n0 + a) * DD + k0 + tx] = __float2half(v - __half2float(h));
    }
}

// =================================================================
// HMMA fp16 GEMM, 128x128 tile, BK=32, 3-stage cp.async pipeline.
// PASSES 2: A split hi/lo, B single     (c += Ahi*B + Alo*B)
// PASSES 3: A split hi/lo, B split      (c += Ahi*Bhi + Ahi*Blo + Alo*Bhi)
// MODE 0: top2(psq - 2*dot) -> g_top2
// MODE 1: +bias, leaky -> outp stride PP
// MODE 2: plain store  -> outp stride DD
// =================================================================
template <int PASSES, int MODE>
__global__ __launch_bounds__(256)
void hmma_gemm_kernel(const __half* __restrict__ Ahi, const __half* __restrict__ Alo,
                      const __half* __restrict__ Bhi, const __half* __restrict__ Blo,
                      const float* __restrict__ bias, float* __restrict__ outp)
{
    constexpr int TILES = (PASSES == 3) ? 4 : 3;
    constexpr int STB = TILES * 8192;
    extern __shared__ char smem[];
    const uint32_t sb = smem_u32(smem);
    const int tid = threadIdx.x;
    const int lane = tid & 31;
    const int w = tid >> 5;
    const int wm = w & 3;
    const int wn = w >> 2;
    const int row0 = blockIdx.y * 128;
    const int col0 = blockIdx.x * 128;

    const int q  = lane >> 3;
    const int lr = lane & 7;
    const int achk = q >> 1;
    const int bchk = q & 1;
    int arow[2], brow[4];
#pragma unroll
    for (int mi = 0; mi < 2; mi++) arow[mi] = wm*32 + mi*16 + ((q & 1) << 3) + lr;
#pragma unroll
    for (int ng = 0; ng < 4; ng++) brow[ng] = wn*64 + ng*16 + ((q >> 1) << 3) + lr;

    float c[2][8][4];
#pragma unroll
    for (int mi = 0; mi < 2; mi++)
#pragma unroll
        for (int nf = 0; nf < 8; nf++)
#pragma unroll
            for (int j = 0; j < 4; j++) c[mi][nf][j] = 0.f;

    auto issue = [&](int st, int kt) {
        const int k0 = kt << 5;
        const uint32_t sbase = sb + st * STB;
#pragma unroll
        for (int it = 0; it < TILES * 2; it++) {
            int ch = it * 256 + tid;
            int t = ch >> 9;
            int within = ch & 511;
            int r = within >> 2, cc = within & 3;
            const __half* src = (t == 0) ? Ahi : (t == 1) ? Alo : (t == 2) ? Bhi : Blo;
            int rbase = (t < 2) ? row0 : col0;
            const void* g = src + (size_t)(rbase + r) * DD + k0 + cc * 8;
            uint32_t s = sbase + t * 8192 + r * 64 + ((cc ^ ((r >> 1) & 3)) << 4);
            asm volatile("cp.async.cg.shared.global [%0], [%1], 16;" :: "r"(s), "l"(g));
        }
        asm volatile("cp.async.commit_group;" ::: "memory");
    };

    auto compute = [&](int st) {
        const uint32_t sbase = sb + st * STB;
#pragma unroll
        for (int ks = 0; ks < 2; ks++) {
            uint32_t ah[2][4], al[2][4], bh[4][4], bl[4][4];
#pragma unroll
            for (int mi = 0; mi < 2; mi++) {
                uint32_t ra = sbase + arow[mi] * 64 +
                              ((((ks << 1) | achk) ^ ((arow[mi] >> 1) & 3)) << 4);
                ldsm4(ah[mi], ra);
                ldsm4(al[mi], ra + 8192);
            }
#pragma unroll
            for (int ng = 0; ng < 4; ng++) {
                uint32_t rb = sbase + 2 * 8192 + brow[ng] * 64 +
                              ((((ks << 1) | bchk) ^ ((brow[ng] >> 1) & 3)) << 4);
                ldsm4(bh[ng], rb);
                if (PASSES == 3) ldsm4(bl[ng], rb + 8192);
            }
#pragma unroll
            for (int mi = 0; mi < 2; mi++)
#pragma unroll
                for (int ng = 0; ng < 4; ng++)
#pragma unroll
                    for (int h = 0; h < 2; h++) {
                        int nf = ng * 2 + h;
                        mma16816(c[mi][nf], ah[mi], bh[ng][h*2], bh[ng][h*2+1]);
                        if (PASSES == 3)
                            mma16816(c[mi][nf], ah[mi], bl[ng][h*2], bl[ng][h*2+1]);
                        mma16816(c[mi][nf], al[mi], bh[ng][h*2], bh[ng][h*2+1]);
                    }
        }
    };

    const int NK = DD / 32;
    issue(0, 0);
    issue(1, 1);
    for (int kt = 0; kt < NK; kt++) {
        if (kt == NK - 1) asm volatile("cp.async.wait_group 0;" ::: "memory");
        else              asm volatile("cp.async.wait_group 1;" ::: "memory");
        __syncthreads();
        compute(kt % NSTAGE);
        if (kt + 2 < NK) issue((kt + 2) % NSTAGE, kt + 2);
        __syncthreads();
    }
    __syncthreads();

    if (MODE == 0) {
        float4* mbuf = reinterpret_cast<float4*>(smem);
#pragma unroll
        for (int mi = 0; mi < 2; mi++)
#pragma unroll
            for (int rh = 0; rh < 2; rh++) {
                int lrow_ = wm*32 + mi*16 + rh*8 + (lane >> 2);
                float v1 = 3.4e38f, v2 = 3.4e38f;
                int i1 = 0, i2 = 0;
#pragma unroll
                for (int nf = 0; nf < 8; nf++) {
                    int col = col0 + wn*64 + nf*8 + ((lane & 3) << 1);
                    float s0 = bias[col]     - 2.f * c[mi][nf][rh*2];
                    float s1 = bias[col + 1] - 2.f * c[mi][nf][rh*2+1];
                    top2_upd(s0, col,     v1, i1, v2, i2);
                    top2_upd(s1, col + 1, v1, i1, v2, i2);
                }
#pragma unroll
                for (int d = 1; d <= 2; d <<= 1) {
                    float w1 = __shfl_xor_sync(0xffffffffu, v1, d);
                    float w2 = __shfl_xor_sync(0xffffffffu, v2, d);
                    int   j1 = __shfl_xor_sync(0xffffffffu, i1, d);
                    int   j2 = __shfl_xor_sync(0xffffffffu, i2, d);
                    top2_merge(w1, j1, w2, j2, v1, i1, v2, i2);
                }
                if ((lane & 3) == 0)
                    mbuf[lrow_ * 2 + wn] =
                        make_float4(v1, __int_as_float(i1), v2, __int_as_float(i2));
            }
        __syncthreads();
        if (tid < 128) {
            float4 a = mbuf[tid * 2 + 0];
            float4 b = mbuf[tid * 2 + 1];
            float v1 = a.x, v2 = a.z;
            int i1 = __float_as_int(a.y), i2 = __float_as_int(a.w);
            top2_merge(b.x, __float_as_int(b.y), b.z, __float_as_int(b.w), v1, i1, v2, i2);
            reinterpret_cast<float4*>(outp)[(size_t)(row0 + tid) * NTIL + blockIdx.x] =
                make_float4(v1, __int_as_float(i1), v2, __int_as_float(i2));
        }
    } else {
        const int NSTRIDE = (MODE == 1) ? PP : DD;
#pragma unroll
        for (int mi = 0; mi < 2; mi++)
#pragma unroll
            for (int rh = 0; rh < 2; rh++) {
                int r = row0 + wm*32 + mi*16 + rh*8 + (lane >> 2);
#pragma unroll
                for (int nf = 0; nf < 8; nf++) {
                    int col = col0 + wn*64 + nf*8 + ((lane & 3) << 1);
                    float v0 = c[mi][nf][rh*2];
                    float v1 = c[mi][nf][rh*2+1];
                    if (MODE == 1) {
                        v0 += bias[col];
                        v1 += bias[col + 1];
                        v0 = v0 > 0.f ? v0 : 0.01f * v0;
                        v1 = v1 > 0.f ? v1 : 0.01f * v1;
                    }
                    float2 o = {v0, v1};
                    *reinterpret_cast<float2*>(&outp[(size_t)r * NSTRIDE + col]) = o;
                }
            }
    }
}

// =================================================================
// merge per-tile top2 + exact rescue for near-ties
// =================================================================
__global__ __launch_bounds__(256)
void argmin_reduce_kernel(const float* __restrict__ patient, const float* __restrict__ protos)
{
    int w = (blockIdx.x * 256 + threadIdx.x) >> 5;
    int lane = threadIdx.x & 31;
    if (w >= BB) return;
    float v1 = 0.f, v2 = 0.f; int i1 = 0, i2 = 0;
    if (lane == 0) {
        v1 = 3.4e38f; v2 = 3.4e38f;
        for (int t = 0; t < NTIL; t++) {
            float4 qd = g_top2[(size_t)w * NTIL + t];
            top2_merge(qd.x, __float_as_int(qd.y), qd.z, __float_as_int(qd.w), v1, i1, v2, i2);
        }
    }
    v1 = __shfl_sync(0xffffffffu, v1, 0);
    v2 = __shfl_sync(0xffffffffu, v2, 0);
    i1 = __shfl_sync(0xffffffffu, i1, 0);
    i2 = __shfl_sync(0xffffffffu, i2, 0);
    if (v2 - v1 >= MARGIN) {
        if (lane == 0) g_labels[w] = i1;
        return;
    }
    const float* x  = patient + (size_t)w * DD;
    const float* pA = protos + (size_t)i1 * DD;
    const float* pB = protos + (size_t)i2 * DD;
    double da = 0.0, db = 0.0;
    for (int k = lane; k < DD; k += 32) {
        double xv = x[k];
        da += xv * (double)pA[k];
        db += xv * (double)pB[k];
    }
#pragma unroll
    for (int off = 16; off; off >>= 1) {
        da += __shfl_down_sync(0xffffffffu, da, off);
        db += __shfl_down_sync(0xffffffffu, db, off);
    }
    if (lane == 0) {
        double sA = (double)g_psq[i1] - 2.0 * da;
        double sB = (double)g_psq[i2] - 2.0 * db;
        bool pickA = (sA < sB) || (sA == sB && i1 < i2);
        g_labels[w] = pickA ? i1 : i2;
    }
}

// =================================================================
// lam[b] = sigmoid(PW[la].protos[lb] + bil_b + v1[la] + v2[lb])
// =================================================================
__global__ __launch_bounds__(256)
void lam_kernel(const int* __restrict__ index, const float* __restrict__ bilinear_b,
                const float* __restrict__ protos)
{
    int w = (blockIdx.x * 256 + threadIdx.x) >> 5;
    int lane = threadIdx.x & 31;
    if (w >= BB) return;
    int la = g_labels[w];
    int lb = g_labels[index[w]];
    const float4* a = reinterpret_cast<const float4*>(g_PW + (size_t)la * DD);
    const float4* p = reinterpret_cast<const float4*>(protos + (size_t)lb * DD);
    float acc = 0.f;
    for (int k = lane; k < DD / 4; k += 32) {
        float4 u = a[k], v = p[k];
        acc = fmaf(u.x, v.x, acc); acc = fmaf(u.y, v.y, acc);
        acc = fmaf(u.z, v.z, acc); acc = fmaf(u.w, v.w, acc);
    }
#pragma unroll
    for (int off = 16; off; off >>= 1) acc += __shfl_down_sync(0xffffffffu, acc, off);
    if (lane == 0) {
        float s = acc + bilinear_b[0] + g_v1[la] + g_v2[lb];
        g_lam[w] = 1.f / (1.f + expf(-s));
    }
}

// =================================================================
// mixed = lam*x + (1-lam)*x[index]; emit fp16 hi/lo
// =================================================================
__global__ __launch_bounds__(256)
void mix_kernel(const float* __restrict__ patient, const int* __restrict__ index)
{
    int b = blockIdx.x;
    float lam = g_lam[b], oml = 1.f - lam;
    int ib = index[b];
    int t = threadIdx.x;
    float4 a = reinterpret_cast<const float4*>(patient + (size_t)b * DD)[t];
    float4 c = reinterpret_cast<const float4*>(patient + (size_t)ib * DD)[t];
    float m0 = lam * a.x + oml * c.x, m1 = lam * a.y + oml * c.y;
    float m2 = lam * a.z + oml * c.z, m3 = lam * a.w + oml * c.w;
    uint32_t h0 = pk2h(m0, m1), h1 = pk2h(m2, m3);
    __half2* hv0 = reinterpret_cast<__half2*>(&h0);
    __half2* hv1 = reinterpret_cast<__half2*>(&h1);
    uint32_t l0 = pk2h(m0 - __half2float(hv0->x), m1 - __half2float(hv0->y));
    uint32_t l1 = pk2h(m2 - __half2float(hv1->x), m3 - __half2float(hv1->y));
    size_t o = (size_t)b * (DD / 2) + 2 * t;
    reinterpret_cast<uint32_t*>(g_mx_hi)[o]     = h0;
    reinterpret_cast<uint32_t*>(g_mx_hi)[o + 1] = h1;
    reinterpret_cast<uint32_t*>(g_mx_lo)[o]     = l0;
    reinterpret_cast<uint32_t*>(g_mx_lo)[o + 1] = l1;
}

// =================================================================
// class head (warp per row)
// =================================================================
__global__ __launch_bounds__(256)
void class_kernel(const float* __restrict__ cw, const float* __restrict__ cb,
                  float* __restrict__ out)
{
    int gw = (blockIdx.x * 256 + threadIdx.x) >> 5;
    int lane = threadIdx.x & 31;
    if (gw >= BB) return;
    const float* lrow = g_logits + (size_t)gw * PP;
    float acc[OUTC];
#pragma unroll
    for (int o = 0; o < OUTC; o++) acc[o] = 0.f;
    for (int p = lane; p < PP; p += 32) {
        float v = lrow[p];
#pragma unroll
        for (int o = 0; o < OUTC; o++) acc[o] = fmaf(v, cw[o * PP + p], acc[o]);
    }
#pragma unroll
    for (int o = 0; o < OUTC; o++)
        for (int off = 16; off; off >>= 1)
            acc[o] += __shfl_down_sync(0xffffffffu, acc[o], off);
    if (lane == 0)
#pragma unroll
        for (int o = 0; o < OUTC; o++)
            out[(size_t)gw * OUTC + o] = acc[o] + cb[o];
}

// =================================================================
// launch
// =================================================================
extern "C" void kernel_launch(void* const* d_in, const int* in_sizes, int n_in,
                              void* d_out, int out_size)
{
    const float* patient    = (const float*)d_in[0];
    const float* protos     = (const float*)d_in[1];
    const int*   index      = (const int*)  d_in[2];
    const float* bilinear_w = (const float*)d_in[3];
    const float* bilinear_b = (const float*)d_in[4];
    const float* lin_w      = (const float*)d_in[5];
    const float* proto_fc_w = (const float*)d_in[6];
    const float* proto_fc_b = (const float*)d_in[7];
    const float* class_fc_w = (const float*)d_in[8];
    const float* class_fc_b = (const float*)d_in[9];
    float* out = (float*)d_out;

    float *pPW, *pPsq, *pLogits;
    float4* pTop2;
    __half *pPaHi, *pPaLo, *pPrHi, *pPrLo, *pFcHi, *pFcLo, *pWtHi, *pWtLo, *pMxHi, *pMxLo;
    cudaGetSymbolAddress((void**)&pPW, g_PW);
    cudaGetSymbolAddress((void**)&pPsq, g_psq);
    cudaGetSymbolAddress((void**)&pLogits, g_logits);
    cudaGetSymbolAddress((void**)&pTop2, g_top2);
    cudaGetSymbolAddress((void**)&pPaHi, g_pa_hi);
    cudaGetSymbolAddress((void**)&pPaLo, g_pa_lo);
    cudaGetSymbolAddress((void**)&pPrHi, g_pr_hi);
    cudaGetSymbolAddress((void**)&pPrLo, g_pr_lo);
    cudaGetSymbolAddress((void**)&pFcHi, g_fc_hi);
    cudaGetSymbolAddress((void**)&pFcLo, g_fc_lo);
    cudaGetSymbolAddress((void**)&pWtHi, g_wt_hi);
    cudaGetSymbolAddress((void**)&pWtLo, g_wt_lo);
    cudaGetSymbolAddress((void**)&pMxHi, g_mx_hi);
    cudaGetSymbolAddress((void**)&pMxLo, g_mx_lo);

    const int SM2 = NSTAGE * 3 * 8192 + 4096;   // 77824
    const int SM3 = NSTAGE * 4 * 8192 + 4096;   // 102400
    cudaFuncSetAttribute(hmma_gemm_kernel<2,0>, cudaFuncAttributeMaxDynamicSharedMemorySize, SM2);
    cudaFuncSetAttribute(hmma_gemm_kernel<2,1>, cudaFuncAttributeMaxDynamicSharedMemorySize, SM2);
    cudaFuncSetAttribute(hmma_gemm_kernel<3,2>, cudaFuncAttributeMaxDynamicSharedMemorySize, SM3);

    prep_kernel<<<PP, 256>>>(protos, lin_w);

    split_kernel<<<(BB * DD / 4) / 256, 256>>>(patient, pPaHi, pPaLo, BB * DD / 4);
    split_kernel<<<(PP * DD / 4) / 256, 256>>>(protos, pPrHi, pPrLo, PP * DD / 4);
    split_kernel<<<(PP * DD / 4) / 256, 256>>>(proto_fc_w, pFcHi, pFcLo, PP * DD / 4);
    splitT_kernel<<<dim3(32, 32), 256>>>(bilinear_w, pWtHi, pWtLo);

    // PW = protos @ W  (3-pass: both operands split, lam path stays accurate)
    hmma_gemm_kernel<3,2><<<dim3(DD / 128, PP / 128), 256, SM3>>>(
        pPrHi, pPrLo, pWtHi, pWtLo, nullptr, pPW);

    // distance GEMM (2-pass, B = fl16(protos)) + per-tile top2
    hmma_gemm_kernel<2,0><<<dim3(PP / 128, BB / 128), 256, SM2>>>(
        pPaHi, pPaLo, pPrHi, nullptr, pPsq, (float*)pTop2);

    argmin_reduce_kernel<<<BB / 8, 256>>>(patient, protos);

    lam_kernel<<<BB / 8, 256>>>(index, bilinear_b, protos);

    mix_kernel<<<BB, 256>>>(patient, index);

    // logits GEMM (2-pass, B = fl16(proto_fc_w); +bias, leaky)
    hmma_gemm_kernel<2,1><<<dim3(PP / 128, BB / 128), 256, SM2>>>(
        pMxHi, pMxLo, pFcHi, nullptr, proto_fc_b, pLogits);

    class_kernel<<<BB / 8, 256>>>(class_fc_w, class_fc_b, out);
}

// round 7
// speedup vs baseline: 1.6752x; 1.0609x over previous
#include <cuda_runtime.h>
#include <cuda_fp16.h>
#include <math.h>
#include <stdint.h>

#define BB   16384
#define DD   1024
#define PP   1024
#define OUTC 25
#define NTIL 8
#define NCAND 16            // float4 slots per row (2 candidates each = 32)
#define MARGIN 0.35f
#define NSTAGE 3

// ---------------- device scratch ----------------
__device__ float g_psq[PP];
__device__ float g_v1[PP];
__device__ float g_v2[PP];
__device__ float g_PW[PP * DD];
__device__ int   g_labels[BB];
__device__ float g_lam[BB];
__device__ float g_logits[(size_t)BB * PP];
__device__ float4 g_top2[(size_t)BB * NCAND];

__device__ __half g_pa_hi[(size_t)BB * DD];
__device__ __half g_pr_hi[(size_t)PP * DD];
__device__ __half g_pr_lo[(size_t)PP * DD];
__device__ __half g_fc_hi[(size_t)PP * DD];
__device__ __half g_wt_hi[(size_t)DD * DD];
__device__ __half g_wt_lo[(size_t)DD * DD];
__device__ __half g_mx_hi[(size_t)BB * DD];
__device__ __half g_mx_lo[(size_t)BB * DD];

// ---------------- helpers ----------------
__device__ __forceinline__ uint32_t smem_u32(const void* p) {
    uint32_t a;
    asm("{ .reg .u64 t; cvta.to.shared.u64 t, %1; cvt.u32.u64 %0, t; }" : "=r"(a) : "l"(p));
    return a;
}
__device__ __forceinline__ void ldsm4(uint32_t r[4], uint32_t addr) {
    asm volatile("ldmatrix.sync.aligned.m8n8.x4.shared.b16 {%0,%1,%2,%3}, [%4];"
                 : "=r"(r[0]), "=r"(r[1]), "=r"(r[2]), "=r"(r[3]) : "r"(addr));
}
__device__ __forceinline__ void mma16816(float c[4], const uint32_t a[4],
                                         uint32_t b0, uint32_t b1) {
    asm volatile("mma.sync.aligned.m16n8k16.row.col.f32.f16.f16.f32 "
                 "{%0,%1,%2,%3}, {%4,%5,%6,%7}, {%8,%9}, {%0,%1,%2,%3};"
                 : "+f"(c[0]), "+f"(c[1]), "+f"(c[2]), "+f"(c[3])
                 : "r"(a[0]), "r"(a[1]), "r"(a[2]), "r"(a[3]), "r"(b0), "r"(b1));
}
__device__ __forceinline__ uint32_t pk2h(float a, float b) {
    __half2 t;
    t.x = __float2half(a); t.y = __float2half(b);
    return *reinterpret_cast<uint32_t*>(&t);
}
__device__ __forceinline__ void top2_upd(float s, int idx, float& v1, int& i1,
                                         float& v2, int& i2) {
    if (s < v1 || (s == v1 && idx < i1)) { v2 = v1; i2 = i1; v1 = s; i1 = idx; }
    else if (s < v2 || (s == v2 && idx < i2)) { v2 = s; i2 = idx; }
}
__device__ __forceinline__ void top2_merge(float w1, int j1, float w2, int j2,
                                           float& v1, int& i1, float& v2, int& i2) {
    top2_upd(w1, j1, v1, i1, v2, i2);
    top2_upd(w2, j2, v1, i1, v2, i2);
}

// =================================================================
// prep: p_sq, v1, v2
// =================================================================
__global__ __launch_bounds__(256) void prep_kernel(
    const float* __restrict__ protos, const float* __restrict__ lin_w)
{
    int p = blockIdx.x, t = threadIdx.x;
    float sq = 0.f, a1 = 0.f, a2 = 0.f;
    const float* row = protos + (size_t)p * DD;
    for (int k = t; k < DD; k += 256) {
        float v = row[k];
        sq = fmaf(v, v, sq);
        a1 = fmaf(v, lin_w[k], a1);
        a2 = fmaf(v, lin_w[DD + k], a2);
    }
    __shared__ float s1[256], s2[256], s3[256];
    s1[t] = sq; s2[t] = a1; s3[t] = a2;
    __syncthreads();
    for (int off = 128; off; off >>= 1) {
        if (t < off) { s1[t] += s1[t+off]; s2[t] += s2[t+off]; s3[t] += s3[t+off]; }
        __syncthreads();
    }
    if (t == 0) { g_psq[p] = s1[0]; g_v1[p] = s2[0]; g_v2[p] = s3[0]; }
}

// =================================================================
// convert fp32 -> fp16 (hi only)
// =================================================================
__global__ __launch_bounds__(256) void convert_kernel(
    const float* __restrict__ src, __half* __restrict__ hi, int n4)
{
    int i = blockIdx.x * 256 + threadIdx.x;
    if (i >= n4) return;
    float4 v = reinterpret_cast<const float4*>(src)[i];
    reinterpret_cast<uint32_t*>(hi)[2*i]   = pk2h(v.x, v.y);
    reinterpret_cast<uint32_t*>(hi)[2*i+1] = pk2h(v.z, v.w);
}

// =================================================================
// split fp32 -> fp16 hi + lo
// =================================================================
__global__ __launch_bounds__(256) void split_kernel(
    const float* __restrict__ src, __half* __restrict__ hi,
    __half* __restrict__ lo, int n4)
{
    int i = blockIdx.x * 256 + threadIdx.x;
    if (i >= n4) return;
    float4 v = reinterpret_cast<const float4*>(src)[i];
    uint32_t h0 = pk2h(v.x, v.y), h1 = pk2h(v.z, v.w);
    __half2* hv0 = reinterpret_cast<__half2*>(&h0);
    __half2* hv1 = reinterpret_cast<__half2*>(&h1);
    uint32_t l0 = pk2h(v.x - __half2float(hv0->x), v.y - __half2float(hv0->y));
    uint32_t l1 = pk2h(v.z - __half2float(hv1->x), v.w - __half2float(hv1->y));
    reinterpret_cast<uint32_t*>(hi)[2*i]   = h0;
    reinterpret_cast<uint32_t*>(hi)[2*i+1] = h1;
    reinterpret_cast<uint32_t*>(lo)[2*i]   = l0;
    reinterpret_cast<uint32_t*>(lo)[2*i+1] = l1;
}

// =================================================================
// transpose + split: WT[n][k] = W[k][n], fp16 hi/lo
// =================================================================
__global__ __launch_bounds__(256) void splitT_kernel(
    const float* __restrict__ W, __half* __restrict__ hiT,
    __half* __restrict__ loT)
{
    __shared__ float tile[32][33];
    int n0 = blockIdx.x * 32, k0 = blockIdx.y * 32;
    int tx = threadIdx.x & 31, ty = threadIdx.x >> 5;
#pragma unroll
    for (int i = 0; i < 4; i++) {
        int kk = ty + i * 8;
        tile[kk][tx] = W[(size_t)(k0 + kk) * DD + n0 + tx];
    }
    __syncthreads();
#pragma unroll
    for (int i = 0; i < 4; i++) {
        int a = ty + i * 8;
        float v = tile[tx][a];
        __half h = __float2half(v);
        hiT[(size_t)(n0 + a) * DD + k0 + tx] = h;
        loT[(size_t)(n0 + a) * DD + k0 + tx] = __float2half(v - __half2float(h));
    }
}

// =================================================================
// HMMA fp16 GEMM, 128x128 tile, BK=32, 3-stage cp.async pipeline.
// PASSES 1: A single, B single
// PASSES 2: A split hi/lo, B single
// PASSES 3: A split hi/lo, B split
// MODE 0: per-warp (64-col) top2(psq - 2*dot) -> g_top2[B][NCAND]
// MODE 1: +bias, leaky -> outp stride PP
// MODE 2: plain store  -> outp stride DD
// =================================================================
template <int PASSES, int MODE>
__global__ __launch_bounds__(256)
void hmma_gemm_kernel(const __half* __restrict__ Ahi, const __half* __restrict__ Alo,
                      const __half* __restrict__ Bhi, const __half* __restrict__ Blo,
                      const float* __restrict__ bias, float* __restrict__ outp)
{
    constexpr int TILES = (PASSES == 3) ? 4 : (PASSES == 2) ? 3 : 2;
    constexpr int STB = TILES * 8192;
    constexpr int BOFF = (PASSES == 1) ? 8192 : 16384;
    extern __shared__ char smem[];
    const uint32_t sb = smem_u32(smem);
    const int tid = threadIdx.x;
    const int lane = tid & 31;
    const int w = tid >> 5;
    const int wm = w & 3;
    const int wn = w >> 2;
    const int row0 = blockIdx.y * 128;
    const int col0 = blockIdx.x * 128;

    const int q  = lane >> 3;
    const int lr = lane & 7;
    const int achk = q >> 1;
    const int bchk = q & 1;
    int arow[2], brow[4];
#pragma unroll
    for (int mi = 0; mi < 2; mi++) arow[mi] = wm*32 + mi*16 + ((q & 1) << 3) + lr;
#pragma unroll
    for (int ng = 0; ng < 4; ng++) brow[ng] = wn*64 + ng*16 + ((q >> 1) << 3) + lr;

    float c[2][8][4];
#pragma unroll
    for (int mi = 0; mi < 2; mi++)
#pragma unroll
        for (int nf = 0; nf < 8; nf++)
#pragma unroll
            for (int j = 0; j < 4; j++) c[mi][nf][j] = 0.f;

    auto issue = [&](int st, int kt) {
        const int k0 = kt << 5;
        const uint32_t sbase = sb + st * STB;
#pragma unroll
        for (int it = 0; it < TILES * 2; it++) {
            int ch = it * 256 + tid;
            int t = ch >> 9;
            int within = ch & 511;
            int r = within >> 2, cc = within & 3;
            const __half* src;
            int rbase;
            if (PASSES == 1) {
                src = (t == 0) ? Ahi : Bhi;
                rbase = (t == 0) ? row0 : col0;
            } else {
                src = (t == 0) ? Ahi : (t == 1) ? Alo : (t == 2) ? Bhi : Blo;
                rbase = (t < 2) ? row0 : col0;
            }
            const void* g = src + (size_t)(rbase + r) * DD + k0 + cc * 8;
            uint32_t s = sbase + t * 8192 + r * 64 + ((cc ^ ((r >> 1) & 3)) << 4);
            asm volatile("cp.async.cg.shared.global [%0], [%1], 16;" :: "r"(s), "l"(g));
        }
        asm volatile("cp.async.commit_group;" ::: "memory");
    };

    auto compute = [&](int st) {
        const uint32_t sbase = sb + st * STB;
#pragma unroll
        for (int ks = 0; ks < 2; ks++) {
            uint32_t ah[2][4], al[2][4], bh[4][4], bl[4][4];
#pragma unroll
            for (int mi = 0; mi < 2; mi++) {
                uint32_t ra = sbase + arow[mi] * 64 +
                              ((((ks << 1) | achk) ^ ((arow[mi] >> 1) & 3)) << 4);
                ldsm4(ah[mi], ra);
                if (PASSES >= 2) ldsm4(al[mi], ra + 8192);
            }
#pragma unroll
            for (int ng = 0; ng < 4; ng++) {
                uint32_t rb = sbase + BOFF + brow[ng] * 64 +
                              ((((ks << 1) | bchk) ^ ((brow[ng] >> 1) & 3)) << 4);
                ldsm4(bh[ng], rb);
                if (PASSES == 3) ldsm4(bl[ng], rb + 8192);
            }
#pragma unroll
            for (int mi = 0; mi < 2; mi++)
#pragma unroll
                for (int ng = 0; ng < 4; ng++)
#pragma unroll
                    for (int h = 0; h < 2; h++) {
                        int nf = ng * 2 + h;
                        mma16816(c[mi][nf], ah[mi], bh[ng][h*2], bh[ng][h*2+1]);
                        if (PASSES == 3)
                            mma16816(c[mi][nf], ah[mi], bl[ng][h*2], bl[ng][h*2+1]);
                        if (PASSES >= 2)
                            mma16816(c[mi][nf], al[mi], bh[ng][h*2], bh[ng][h*2+1]);
                    }
        }
    };

    const int NK = DD / 32;
    issue(0, 0);
    issue(1, 1);
    for (int kt = 0; kt < NK; kt++) {
        if (kt == NK - 1) asm volatile("cp.async.wait_group 0;" ::: "memory");
        else              asm volatile("cp.async.wait_group 1;" ::: "memory");
        __syncthreads();
        compute(kt % NSTAGE);
        if (kt + 2 < NK) issue((kt + 2) % NSTAGE, kt + 2);
        __syncthreads();
    }
    __syncthreads();

    if (MODE == 0) {
        // per-warp (64-col) top2, stored directly: 2 float4 per row per tile
#pragma unroll
        for (int mi = 0; mi < 2; mi++)
#pragma unroll
            for (int rh = 0; rh < 2; rh++) {
                int lrow_ = wm*32 + mi*16 + rh*8 + (lane >> 2);
                float v1 = 3.4e38f, v2 = 3.4e38f;
                int i1 = 0, i2 = 0;
#pragma unroll
                for (int nf = 0; nf < 8; nf++) {
                    int col = col0 + wn*64 + nf*8 + ((lane & 3) << 1);
                    float s0 = bias[col]     - 2.f * c[mi][nf][rh*2];
                    float s1 = bias[col + 1] - 2.f * c[mi][nf][rh*2+1];
                    top2_upd(s0, col,     v1, i1, v2, i2);
                    top2_upd(s1, col + 1, v1, i1, v2, i2);
                }
#pragma unroll
                for (int d = 1; d <= 2; d <<= 1) {
                    float w1 = __shfl_xor_sync(0xffffffffu, v1, d);
                    float w2 = __shfl_xor_sync(0xffffffffu, v2, d);
                    int   j1 = __shfl_xor_sync(0xffffffffu, i1, d);
                    int   j2 = __shfl_xor_sync(0xffffffffu, i2, d);
                    top2_merge(w1, j1, w2, j2, v1, i1, v2, i2);
                }
                if ((lane & 3) == 0)
                    reinterpret_cast<float4*>(outp)[(size_t)(row0 + lrow_) * NCAND
                                                    + blockIdx.x * 2 + wn] =
                        make_float4(v1, __int_as_float(i1), v2, __int_as_float(i2));
            }
    } else {
        const int NSTRIDE = (MODE == 1) ? PP : DD;
#pragma unroll
        for (int mi = 0; mi < 2; mi++)
#pragma unroll
            for (int rh = 0; rh < 2; rh++) {
                int r = row0 + wm*32 + mi*16 + rh*8 + (lane >> 2);
#pragma unroll
                for (int nf = 0; nf < 8; nf++) {
                    int col = col0 + wn*64 + nf*8 + ((lane & 3) << 1);
                    float v0 = c[mi][nf][rh*2];
                    float v1 = c[mi][nf][rh*2+1];
                    if (MODE == 1) {
                        v0 += bias[col];
                        v1 += bias[col + 1];
                        v0 = v0 > 0.f ? v0 : 0.01f * v0;
                        v1 = v1 > 0.f ? v1 : 0.01f * v1;
                    }
                    float2 o = {v0, v1};
                    *reinterpret_cast<float2*>(&outp[(size_t)r * NSTRIDE + col]) = o;
                }
            }
    }
}

// =================================================================
// 32 candidates/row (one per lane); exact fp64 rescue over all
// candidates within MARGIN of the approximate min
// =================================================================
__global__ __launch_bounds__(256)
void argmin_reduce_kernel(const float* __restrict__ patient, const float* __restrict__ protos)
{
    int w = (blockIdx.x * 256 + threadIdx.x) >> 5;
    int lane = threadIdx.x & 31;
    if (w >= BB) return;

    float4 qd = g_top2[(size_t)w * NCAND + (lane >> 1)];
    float val;
    int idx;
    if (lane & 1) { val = qd.z; idx = __float_as_int(qd.w); }
    else          { val = qd.x; idx = __float_as_int(qd.y); }

    float vmin = val;
#pragma unroll
    for (int d = 16; d; d >>= 1)
        vmin = fminf(vmin, __shfl_xor_sync(0xffffffffu, vmin, d));

    bool flag = (val < vmin + MARGIN);
    unsigned mask = __ballot_sync(0xffffffffu, flag);

    if (__popc(mask) == 1) {
        if (flag) g_labels[w] = idx;
        return;
    }

    const float* x = patient + (size_t)w * DD;
    double bestd = 1.0e300;
    int besti = 0x7FFFFFFF;
    while (mask) {
        int src = __ffs(mask) - 1;
        mask &= mask - 1;
        int ci = __shfl_sync(0xffffffffu, idx, src);
        const float* pr = protos + (size_t)ci * DD;
        double acc = 0.0;
        for (int k = lane; k < DD; k += 32)
            acc += (double)x[k] * (double)pr[k];
#pragma unroll
        for (int d = 16; d; d >>= 1)
            acc += __shfl_down_sync(0xffffffffu, acc, d);
        if (lane == 0) {
            double d2 = (double)g_psq[ci] - 2.0 * acc;
            if (d2 < bestd || (d2 == bestd && ci < besti)) { bestd = d2; besti = ci; }
        }
    }
    if (lane == 0) g_labels[w] = besti;
}

// =================================================================
// lam[b] = sigmoid(PW[la].protos[lb] + bil_b + v1[la] + v2[lb])
// =================================================================
__global__ __launch_bounds__(256)
void lam_kernel(const int* __restrict__ index, const float* __restrict__ bilinear_b,
                const float* __restrict__ protos)
{
    int w = (blockIdx.x * 256 + threadIdx.x) >> 5;
    int lane = threadIdx.x & 31;
    if (w >= BB) return;
    int la = g_labels[w];
    int lb = g_labels[index[w]];
    const float4* a = reinterpret_cast<const float4*>(g_PW + (size_t)la * DD);
    const float4* p = reinterpret_cast<const float4*>(protos + (size_t)lb * DD);
    float acc = 0.f;
    for (int k = lane; k < DD / 4; k += 32) {
        float4 u = a[k], v = p[k];
        acc = fmaf(u.x, v.x, acc); acc = fmaf(u.y, v.y, acc);
        acc = fmaf(u.z, v.z, acc); acc = fmaf(u.w, v.w, acc);
    }
#pragma unroll
    for (int off = 16; off; off >>= 1) acc += __shfl_down_sync(0xffffffffu, acc, off);
    if (lane == 0) {
        float s = acc + bilinear_b[0] + g_v1[la] + g_v2[lb];
        g_lam[w] = 1.f / (1.f + expf(-s));
    }
}

// =================================================================
// mixed = lam*x + (1-lam)*x[index]; emit fp16 hi/lo
// =================================================================
__global__ __launch_bounds__(256)
void mix_kernel(const float* __restrict__ patient, const int* __restrict__ index)
{
    int b = blockIdx.x;
    float lam = g_lam[b], oml = 1.f - lam;
    int ib = index[b];
    int t = threadIdx.x;
    float4 a = reinterpret_cast<const float4*>(patient + (size_t)b * DD)[t];
    float4 c = reinterpret_cast<const float4*>(patient + (size_t)ib * DD)[t];
    float m0 = lam * a.x + oml * c.x, m1 = lam * a.y + oml * c.y;
    float m2 = lam * a.z + oml * c.z, m3 = lam * a.w + oml * c.w;
    uint32_t h0 = pk2h(m0, m1), h1 = pk2h(m2, m3);
    __half2* hv0 = reinterpret_cast<__half2*>(&h0);
    __half2* hv1 = reinterpret_cast<__half2*>(&h1);
    uint32_t l0 = pk2h(m0 - __half2float(hv0->x), m1 - __half2float(hv0->y));
    uint32_t l1 = pk2h(m2 - __half2float(hv1->x), m3 - __half2float(hv1->y));
    size_t o = (size_t)b * (DD / 2) + 2 * t;
    reinterpret_cast<uint32_t*>(g_mx_hi)[o]     = h0;
    reinterpret_cast<uint32_t*>(g_mx_hi)[o + 1] = h1;
    reinterpret_cast<uint32_t*>(g_mx_lo)[o]     = l0;
    reinterpret_cast<uint32_t*>(g_mx_lo)[o + 1] = l1;
}

// =================================================================
// class head: tiled GEMM, 128 rows/block. ALL threads share the same
// kt; inner k-range split by kh (no cross-kt smem sharing -> no race)
// =================================================================
__global__ __launch_bounds__(256)
void class_kernel(const float* __restrict__ cw, const float* __restrict__ cb,
                  float* __restrict__ out)
{
    __shared__ float lt[128][33];
    __shared__ float cws[32][26];
    __shared__ float red[128][26];

    const int tid = threadIdx.x;
    const int row = tid & 127;
    const int kh = tid >> 7;
    const int row0 = blockIdx.x * 128;

    float acc[OUTC];
#pragma unroll
    for (int o = 0; o < OUTC; o++) acc[o] = 0.f;

    for (int kt = 0; kt < PP / 32; kt++) {
#pragma unroll
        for (int i = 0; i < 16; i++) {
            int flat = i * 256 + tid;
            int r = flat >> 5, k = flat & 31;
            lt[r][k] = g_logits[(size_t)(row0 + r) * PP + kt * 32 + k];
        }
#pragma unroll
        for (int i = 0; i < 4; i++) {
            int flat = i * 256 + tid;
            if (flat < 32 * OUTC) {
                int k = flat / OUTC, o = flat % OUTC;
                cws[k][o] = cw[(size_t)o * PP + kt * 32 + k];
            }
        }
        __syncthreads();
#pragma unroll
        for (int kk = 0; kk < 16; kk++) {
            int k = kh * 16 + kk;
            float v = lt[row][k];
#pragma unroll
            for (int o = 0; o < OUTC; o++)
                acc[o] = fmaf(v, cws[k][o], acc[o]);
        }
        __syncthreads();
    }

    if (kh == 1) {
#pragma unroll
        for (int o = 0; o < OUTC; o++) red[row][o] = acc[o];
    }
    __syncthreads();
    if (kh == 0) {
#pragma unroll
        for (int o = 0; o < OUTC; o++)
            out[(size_t)(row0 + row) * OUTC + o] = acc[o] + red[row][o] + cb[o];
    }
}

// =================================================================
// launch
// =================================================================
extern "C" void kernel_launch(void* const* d_in, const int* in_sizes, int n_in,
                              void* d_out, int out_size)
{
    const float* patient    = (const float*)d_in[0];
    const float* protos     = (const float*)d_in[1];
    const int*   index      = (const int*)  d_in[2];
    const float* bilinear_w = (const float*)d_in[3];
    const float* bilinear_b = (const float*)d_in[4];
    const float* lin_w      = (const float*)d_in[5];
    const float* proto_fc_w = (const float*)d_in[6];
    const float* proto_fc_b = (const float*)d_in[7];
    const float* class_fc_w = (const float*)d_in[8];
    const float* class_fc_b = (const float*)d_in[9];
    float* out = (float*)d_out;

    float *pPW, *pPsq, *pLogits;
    float4* pTop2;
    __half *pPaHi, *pPrHi, *pPrLo, *pFcHi, *pWtHi, *pWtLo, *pMxHi, *pMxLo;
    cudaGetSymbolAddress((void**)&pPW, g_PW);
    cudaGetSymbolAddress((void**)&pPsq, g_psq);
    cudaGetSymbolAddress((void**)&pLogits, g_logits);
    cudaGetSymbolAddress((void**)&pTop2, g_top2);
    cudaGetSymbolAddress((void**)&pPaHi, g_pa_hi);
    cudaGetSymbolAddress((void**)&pPrHi, g_pr_hi);
    cudaGetSymbolAddress((void**)&pPrLo, g_pr_lo);
    cudaGetSymbolAddress((void**)&pFcHi, g_fc_hi);
    cudaGetSymbolAddress((void**)&pWtHi, g_wt_hi);
    cudaGetSymbolAddress((void**)&pWtLo, g_wt_lo);
    cudaGetSymbolAddress((void**)&pMxHi, g_mx_hi);
    cudaGetSymbolAddress((void**)&pMxLo, g_mx_lo);

    const int SM1 = NSTAGE * 2 * 8192 + 4096;   // 53248
    const int SM2 = NSTAGE * 3 * 8192 + 4096;   // 77824
    const int SM3 = NSTAGE * 4 * 8192 + 4096;   // 102400
    cudaFuncSetAttribute(hmma_gemm_kernel<1,0>, cudaFuncAttributeMaxDynamicSharedMemorySize, SM1);
    cudaFuncSetAttribute(hmma_gemm_kernel<2,1>, cudaFuncAttributeMaxDynamicSharedMemorySize, SM2);
    cudaFuncSetAttribute(hmma_gemm_kernel<3,2>, cudaFuncAttributeMaxDynamicSharedMemorySize, SM3);

    prep_kernel<<<PP, 256>>>(protos, lin_w);

    convert_kernel<<<(BB * DD / 4) / 256, 256>>>(patient, pPaHi, BB * DD / 4);
    split_kernel<<<(PP * DD / 4) / 256, 256>>>(protos, pPrHi, pPrLo, PP * DD / 4);
    convert_kernel<<<(PP * DD / 4) / 256, 256>>>(proto_fc_w, pFcHi, PP * DD / 4);
    splitT_kernel<<<dim3(32, 32), 256>>>(bilinear_w, pWtHi, pWtLo);

    // PW = protos @ W  (3-pass: lam path stays accurate)
    hmma_gemm_kernel<3,2><<<dim3(DD / 128, PP / 128), 256, SM3>>>(
        pPrHi, pPrLo, pWtHi, pWtLo, nullptr, pPW);

    // distance GEMM (1-pass fp16) + per-warp top2 candidates
    hmma_gemm_kernel<1,0><<<dim3(PP / 128, BB / 128), 256, SM1>>>(
        pPaHi, nullptr, pPrHi, nullptr, pPsq, (float*)pTop2);

    argmin_reduce_kernel<<<BB / 8, 256>>>(patient, protos);

    lam_kernel<<<BB / 8, 256>>>(index, bilinear_b, protos);

    mix_kernel<<<BB, 256>>>(patient, index);

    // logits GEMM (2-pass, B = fl16(proto_fc_w); +bias, leaky)
    hmma_gemm_kernel<2,1><<<dim3(PP / 128, BB / 128), 256, SM2>>>(
        pMxHi, pMxLo, pFcHi, nullptr, proto_fc_b, pLogits);

    class_kernel<<<BB / 128, 256>>>(class_fc_w, class_fc_b, out);
}

// round 8
// speedup vs baseline: 1.9433x; 1.1600x over previous
#include <cuda_runtime.h>
#include <cuda_fp16.h>
#include <math.h>
#include <stdint.h>

#define BB   16384
#define DD   1024
#define PP   1024
#define OUTC 25
#define NCAND 16            // float4 slots per row (2 candidates each = 32)
#define MARGIN 0.35f

// ---------------- device scratch ----------------
__device__ float g_psq[PP];
__device__ float g_v1[PP];
__device__ float g_v2[PP];
__device__ float g_PW[PP * DD];
__device__ int   g_labels[BB];
__device__ float g_lam[BB];
__device__ float g_logits[(size_t)BB * PP];
__device__ float4 g_top2[(size_t)BB * NCAND];

__device__ __half g_pa_hi[(size_t)BB * DD];
__device__ __half g_pr_hi[(size_t)PP * DD];
__device__ __half g_pr_lo[(size_t)PP * DD];
__device__ __half g_fc_hi[(size_t)PP * DD];
__device__ __half g_wt_hi[(size_t)DD * DD];
__device__ __half g_wt_lo[(size_t)DD * DD];
__device__ __half g_mx_hi[(size_t)BB * DD];

// ---------------- helpers ----------------
__device__ __forceinline__ uint32_t smem_u32(const void* p) {
    uint32_t a;
    asm("{ .reg .u64 t; cvta.to.shared.u64 t, %1; cvt.u32.u64 %0, t; }" : "=r"(a) : "l"(p));
    return a;
}
__device__ __forceinline__ void ldsm4(uint32_t r[4], uint32_t addr) {
    asm volatile("ldmatrix.sync.aligned.m8n8.x4.shared.b16 {%0,%1,%2,%3}, [%4];"
                 : "=r"(r[0]), "=r"(r[1]), "=r"(r[2]), "=r"(r[3]) : "r"(addr));
}
__device__ __forceinline__ void mma16816(float c[4], const uint32_t a[4],
                                         uint32_t b0, uint32_t b1) {
    asm volatile("mma.sync.aligned.m16n8k16.row.col.f32.f16.f16.f32 "
                 "{%0,%1,%2,%3}, {%4,%5,%6,%7}, {%8,%9}, {%0,%1,%2,%3};"
                 : "+f"(c[0]), "+f"(c[1]), "+f"(c[2]), "+f"(c[3])
                 : "r"(a[0]), "r"(a[1]), "r"(a[2]), "r"(a[3]), "r"(b0), "r"(b1));
}
__device__ __forceinline__ uint32_t pk2h(float a, float b) {
    __half2 t;
    t.x = __float2half(a); t.y = __float2half(b);
    return *reinterpret_cast<uint32_t*>(&t);
}
__device__ __forceinline__ void top2_upd(float s, int idx, float& v1, int& i1,
                                         float& v2, int& i2) {
    if (s < v1 || (s == v1 && idx < i1)) { v2 = v1; i2 = i1; v1 = s; i1 = idx; }
    else if (s < v2 || (s == v2 && idx < i2)) { v2 = s; i2 = idx; }
}
__device__ __forceinline__ void top2_merge(float w1, int j1, float w2, int j2,
                                           float& v1, int& i1, float& v2, int& i2) {
    top2_upd(w1, j1, v1, i1, v2, i2);
    top2_upd(w2, j2, v1, i1, v2, i2);
}

// =================================================================
// prep: p_sq, v1, v2
// =================================================================
__global__ __launch_bounds__(256) void prep_kernel(
    const float* __restrict__ protos, const float* __restrict__ lin_w)
{
    int p = blockIdx.x, t = threadIdx.x;
    float sq = 0.f, a1 = 0.f, a2 = 0.f;
    const float* row = protos + (size_t)p * DD;
    for (int k = t; k < DD; k += 256) {
        float v = row[k];
        sq = fmaf(v, v, sq);
        a1 = fmaf(v, lin_w[k], a1);
        a2 = fmaf(v, lin_w[DD + k], a2);
    }
    __shared__ float s1[256], s2[256], s3[256];
    s1[t] = sq; s2[t] = a1; s3[t] = a2;
    __syncthreads();
    for (int off = 128; off; off >>= 1) {
        if (t < off) { s1[t] += s1[t+off]; s2[t] += s2[t+off]; s3[t] += s3[t+off]; }
        __syncthreads();
    }
    if (t == 0) { g_psq[p] = s1[0]; g_v1[p] = s2[0]; g_v2[p] = s3[0]; }
}

// =================================================================
// convert fp32 -> fp16 (hi only)
// =================================================================
__global__ __launch_bounds__(256) void convert_kernel(
    const float* __restrict__ src, __half* __restrict__ hi, int n4)
{
    int i = blockIdx.x * 256 + threadIdx.x;
    if (i >= n4) return;
    float4 v = reinterpret_cast<const float4*>(src)[i];
    reinterpret_cast<uint32_t*>(hi)[2*i]   = pk2h(v.x, v.y);
    reinterpret_cast<uint32_t*>(hi)[2*i+1] = pk2h(v.z, v.w);
}

// =================================================================
// split fp32 -> fp16 hi + lo
// =================================================================
__global__ __launch_bounds__(256) void split_kernel(
    const float* __restrict__ src, __half* __restrict__ hi,
    __half* __restrict__ lo, int n4)
{
    int i = blockIdx.x * 256 + threadIdx.x;
    if (i >= n4) return;
    float4 v = reinterpret_cast<const float4*>(src)[i];
    uint32_t h0 = pk2h(v.x, v.y), h1 = pk2h(v.z, v.w);
    __half2* hv0 = reinterpret_cast<__half2*>(&h0);
    __half2* hv1 = reinterpret_cast<__half2*>(&h1);
    uint32_t l0 = pk2h(v.x - __half2float(hv0->x), v.y - __half2float(hv0->y));
    uint32_t l1 = pk2h(v.z - __half2float(hv1->x), v.w - __half2float(hv1->y));
    reinterpret_cast<uint32_t*>(hi)[2*i]   = h0;
    reinterpret_cast<uint32_t*>(hi)[2*i+1] = h1;
    reinterpret_cast<uint32_t*>(lo)[2*i]   = l0;
    reinterpret_cast<uint32_t*>(lo)[2*i+1] = l1;
}

// =================================================================
// transpose + split: WT[n][k] = W[k][n], fp16 hi/lo
// =================================================================
__global__ __launch_bounds__(256) void splitT_kernel(
    const float* __restrict__ W, __half* __restrict__ hiT,
    __half* __restrict__ loT)
{
    __shared__ float tile[32][33];
    int n0 = blockIdx.x * 32, k0 = blockIdx.y * 32;
    int tx = threadIdx.x & 31, ty = threadIdx.x >> 5;
#pragma unroll
    for (int i = 0; i < 4; i++) {
        int kk = ty + i * 8;
        tile[kk][tx] = W[(size_t)(k0 + kk) * DD + n0 + tx];
    }
    __syncthreads();
#pragma unroll
    for (int i = 0; i < 4; i++) {
        int a = ty + i * 8;
        float v = tile[tx][a];
        __half h = __float2half(v);
        hiT[(size_t)(n0 + a) * DD + k0 + tx] = h;
        loT[(size_t)(n0 + a) * DD + k0 + tx] = __float2half(v - __half2float(h));
    }
}

// =================================================================
// HMMA fp16 GEMM, 128x128 tile, BK=32, NST-stage cp.async pipeline
// with (NST-1) groups in flight.
// PASSES 1: A single, B single
// PASSES 3: A split hi/lo, B split
// MODE 0: per-warp (64-col) top2(psq - 2*dot) -> g_top2[B][NCAND]
// MODE 1: +bias, leaky -> outp stride PP
// MODE 2: plain store  -> outp stride DD
// =================================================================
template <int PASSES, int MODE, int NST>
__global__ __launch_bounds__(256)
void hmma_gemm_kernel(const __half* __restrict__ Ahi, const __half* __restrict__ Alo,
                      const __half* __restrict__ Bhi, const __half* __restrict__ Blo,
                      const float* __restrict__ bias, float* __restrict__ outp)
{
    constexpr int TILES = (PASSES == 3) ? 4 : 2;
    constexpr int STB = TILES * 8192;
    constexpr int BOFF = (PASSES == 1) ? 8192 : 16384;
    constexpr int DEPTH = NST - 1;
    extern __shared__ char smem[];
    const uint32_t sb = smem_u32(smem);
    const int tid = threadIdx.x;
    const int lane = tid & 31;
    const int w = tid >> 5;
    const int wm = w & 3;
    const int wn = w >> 2;
    const int row0 = blockIdx.y * 128;
    const int col0 = blockIdx.x * 128;

    const int q  = lane >> 3;
    const int lr = lane & 7;
    const int achk = q >> 1;
    const int bchk = q & 1;
    int arow[2], brow[4];
#pragma unroll
    for (int mi = 0; mi < 2; mi++) arow[mi] = wm*32 + mi*16 + ((q & 1) << 3) + lr;
#pragma unroll
    for (int ng = 0; ng < 4; ng++) brow[ng] = wn*64 + ng*16 + ((q >> 1) << 3) + lr;

    float c[2][8][4];
#pragma unroll
    for (int mi = 0; mi < 2; mi++)
#pragma unroll
        for (int nf = 0; nf < 8; nf++)
#pragma unroll
            for (int j = 0; j < 4; j++) c[mi][nf][j] = 0.f;

    auto issue = [&](int st, int kt) {
        const int k0 = kt << 5;
        const uint32_t sbase = sb + st * STB;
#pragma unroll
        for (int it = 0; it < TILES * 2; it++) {
            int ch = it * 256 + tid;
            int t = ch >> 9;
            int within = ch & 511;
            int r = within >> 2, cc = within & 3;
            const __half* src;
            int rbase;
            if (PASSES == 1) {
                src = (t == 0) ? Ahi : Bhi;
                rbase = (t == 0) ? row0 : col0;
            } else {
                src = (t == 0) ? Ahi : (t == 1) ? Alo : (t == 2) ? Bhi : Blo;
                rbase = (t < 2) ? row0 : col0;
            }
            const void* g = src + (size_t)(rbase + r) * DD + k0 + cc * 8;
            uint32_t s = sbase + t * 8192 + r * 64 + ((cc ^ ((r >> 1) & 3)) << 4);
            asm volatile("cp.async.cg.shared.global [%0], [%1], 16;" :: "r"(s), "l"(g));
        }
        asm volatile("cp.async.commit_group;" ::: "memory");
    };

    auto compute = [&](int st) {
        const uint32_t sbase = sb + st * STB;
#pragma unroll
        for (int ks = 0; ks < 2; ks++) {
            uint32_t ah[2][4], al[2][4], bh[4][4], bl[4][4];
#pragma unroll
            for (int mi = 0; mi < 2; mi++) {
                uint32_t ra = sbase + arow[mi] * 64 +
                              ((((ks << 1) | achk) ^ ((arow[mi] >> 1) & 3)) << 4);
                ldsm4(ah[mi], ra);
                if (PASSES == 3) ldsm4(al[mi], ra + 8192);
            }
#pragma unroll
            for (int ng = 0; ng < 4; ng++) {
                uint32_t rb = sbase + BOFF + brow[ng] * 64 +
                              ((((ks << 1) | bchk) ^ ((brow[ng] >> 1) & 3)) << 4);
                ldsm4(bh[ng], rb);
                if (PASSES == 3) ldsm4(bl[ng], rb + 8192);
            }
#pragma unroll
            for (int mi = 0; mi < 2; mi++)
#pragma unroll
                for (int ng = 0; ng < 4; ng++)
#pragma unroll
                    for (int h = 0; h < 2; h++) {
                        int nf = ng * 2 + h;
                        mma16816(c[mi][nf], ah[mi], bh[ng][h*2], bh[ng][h*2+1]);
                        if (PASSES == 3) {
                            mma16816(c[mi][nf], ah[mi], bl[ng][h*2], bl[ng][h*2+1]);
                            mma16816(c[mi][nf], al[mi], bh[ng][h*2], bh[ng][h*2+1]);
                        }
                    }
        }
    };

    const int NK = DD / 32;
#pragma unroll
    for (int i = 0; i < DEPTH; i++) issue(i, i);
    for (int kt = 0; kt < NK; kt++) {
        const int rem = NK - 1 - kt;   // groups issued beyond kt (clamped by DEPTH-1)
        if (DEPTH == 3) {
            if (rem >= 2)      asm volatile("cp.async.wait_group 2;" ::: "memory");
            else if (rem == 1) asm volatile("cp.async.wait_group 1;" ::: "memory");
            else               asm volatile("cp.async.wait_group 0;" ::: "memory");
        } else {
            if (rem >= 1)      asm volatile("cp.async.wait_group 1;" ::: "memory");
            else               asm volatile("cp.async.wait_group 0;" ::: "memory");
        }
        __syncthreads();
        compute(kt % NST);
        if (kt + DEPTH < NK) issue((kt + DEPTH) % NST, kt + DEPTH);
        __syncthreads();
    }
    __syncthreads();

    if (MODE == 0) {
        // per-warp (64-col) top2, stored directly: 2 float4 per row per tile
#pragma unroll
        for (int mi = 0; mi < 2; mi++)
#pragma unroll
            for (int rh = 0; rh < 2; rh++) {
                int lrow_ = wm*32 + mi*16 + rh*8 + (lane >> 2);
                float v1 = 3.4e38f, v2 = 3.4e38f;
                int i1 = 0, i2 = 0;
#pragma unroll
                for (int nf = 0; nf < 8; nf++) {
                    int col = col0 + wn*64 + nf*8 + ((lane & 3) << 1);
                    float s0 = bias[col]     - 2.f * c[mi][nf][rh*2];
                    float s1 = bias[col + 1] - 2.f * c[mi][nf][rh*2+1];
                    top2_upd(s0, col,     v1, i1, v2, i2);
                    top2_upd(s1, col + 1, v1, i1, v2, i2);
                }
#pragma unroll
                for (int d = 1; d <= 2; d <<= 1) {
                    float w1 = __shfl_xor_sync(0xffffffffu, v1, d);
                    float w2 = __shfl_xor_sync(0xffffffffu, v2, d);
                    int   j1 = __shfl_xor_sync(0xffffffffu, i1, d);
                    int   j2 = __shfl_xor_sync(0xffffffffu, i2, d);
                    top2_merge(w1, j1, w2, j2, v1, i1, v2, i2);
                }
                if ((lane & 3) == 0)
                    reinterpret_cast<float4*>(outp)[(size_t)(row0 + lrow_) * NCAND
                                                    + blockIdx.x * 2 + wn] =
                        make_float4(v1, __int_as_float(i1), v2, __int_as_float(i2));
            }
    } else {
        const int NSTRIDE = (MODE == 1) ? PP : DD;
#pragma unroll
        for (int mi = 0; mi < 2; mi++)
#pragma unroll
            for (int rh = 0; rh < 2; rh++) {
                int r = row0 + wm*32 + mi*16 + rh*8 + (lane >> 2);
#pragma unroll
                for (int nf = 0; nf < 8; nf++) {
                    int col = col0 + wn*64 + nf*8 + ((lane & 3) << 1);
                    float v0 = c[mi][nf][rh*2];
                    float v1 = c[mi][nf][rh*2+1];
                    if (MODE == 1) {
                        v0 += bias[col];
                        v1 += bias[col + 1];
                        v0 = v0 > 0.f ? v0 : 0.01f * v0;
                        v1 = v1 > 0.f ? v1 : 0.01f * v1;
                    }
                    float2 o = {v0, v1};
                    *reinterpret_cast<float2*>(&outp[(size_t)r * NSTRIDE + col]) = o;
                }
            }
    }
}

// =================================================================
// 32 candidates/row (one per lane); exact fp64 rescue over all
// candidates within MARGIN of the approximate min
// =================================================================
__global__ __launch_bounds__(256)
void argmin_reduce_kernel(const float* __restrict__ patient, const float* __restrict__ protos)
{
    int w = (blockIdx.x * 256 + threadIdx.x) >> 5;
    int lane = threadIdx.x & 31;
    if (w >= BB) return;

    float4 qd = g_top2[(size_t)w * NCAND + (lane >> 1)];
    float val;
    int idx;
    if (lane & 1) { val = qd.z; idx = __float_as_int(qd.w); }
    else          { val = qd.x; idx = __float_as_int(qd.y); }

    float vmin = val;
#pragma unroll
    for (int d = 16; d; d >>= 1)
        vmin = fminf(vmin, __shfl_xor_sync(0xffffffffu, vmin, d));

    bool flag = (val < vmin + MARGIN);
    unsigned mask = __ballot_sync(0xffffffffu, flag);

    if (__popc(mask) == 1) {
        if (flag) g_labels[w] = idx;
        return;
    }

    const float* x = patient + (size_t)w * DD;
    double bestd = 1.0e300;
    int besti = 0x7FFFFFFF;
    while (mask) {
        int src = __ffs(mask) - 1;
        mask &= mask - 1;
        int ci = __shfl_sync(0xffffffffu, idx, src);
        const float* pr = protos + (size_t)ci * DD;
        double acc = 0.0;
        for (int k = lane; k < DD; k += 32)
            acc += (double)x[k] * (double)pr[k];
#pragma unroll
        for (int d = 16; d; d >>= 1)
            acc += __shfl_down_sync(0xffffffffu, acc, d);
        if (lane == 0) {
            double d2 = (double)g_psq[ci] - 2.0 * acc;
            if (d2 < bestd || (d2 == bestd && ci < besti)) { bestd = d2; besti = ci; }
        }
    }
    if (lane == 0) g_labels[w] = besti;
}

// =================================================================
// lam[b] = sigmoid(PW[la].protos[lb] + bil_b + v1[la] + v2[lb])
// =================================================================
__global__ __launch_bounds__(256)
void lam_kernel(const int* __restrict__ index, const float* __restrict__ bilinear_b,
                const float* __restrict__ protos)
{
    int w = (blockIdx.x * 256 + threadIdx.x) >> 5;
    int lane = threadIdx.x & 31;
    if (w >= BB) return;
    int la = g_labels[w];
    int lb = g_labels[index[w]];
    const float4* a = reinterpret_cast<const float4*>(g_PW + (size_t)la * DD);
    const float4* p = reinterpret_cast<const float4*>(protos + (size_t)lb * DD);
    float acc = 0.f;
    for (int k = lane; k < DD / 4; k += 32) {
        float4 u = a[k], v = p[k];
        acc = fmaf(u.x, v.x, acc); acc = fmaf(u.y, v.y, acc);
        acc = fmaf(u.z, v.z, acc); acc = fmaf(u.w, v.w, acc);
    }
#pragma unroll
    for (int off = 16; off; off >>= 1) acc += __shfl_down_sync(0xffffffffu, acc, off);
    if (lane == 0) {
        float s = acc + bilinear_b[0] + g_v1[la] + g_v2[lb];
        g_lam[w] = 1.f / (1.f + expf(-s));
    }
}

// =================================================================
// mixed = lam*x + (1-lam)*x[index]; emit fp16 (hi only)
// =================================================================
__global__ __launch_bounds__(256)
void mix_kernel(const float* __restrict__ patient, const int* __restrict__ index)
{
    int b = blockIdx.x;
    float lam = g_lam[b], oml = 1.f - lam;
    int ib = index[b];
    int t = threadIdx.x;
    float4 a = reinterpret_cast<const float4*>(patient + (size_t)b * DD)[t];
    float4 c = reinterpret_cast<const float4*>(patient + (size_t)ib * DD)[t];
    float m0 = lam * a.x + oml * c.x, m1 = lam * a.y + oml * c.y;
    float m2 = lam * a.z + oml * c.z, m3 = lam * a.w + oml * c.w;
    size_t o = (size_t)b * (DD / 2) + 2 * t;
    reinterpret_cast<uint32_t*>(g_mx_hi)[o]     = pk2h(m0, m1);
    reinterpret_cast<uint32_t*>(g_mx_hi)[o + 1] = pk2h(m2, m3);
}

// =================================================================
// class head: tiled GEMM, 128 rows/block. ALL threads share the same
// kt; inner k-range split by kh (no cross-kt smem sharing -> no race)
// =================================================================
__global__ __launch_bounds__(256)
void class_kernel(const float* __restrict__ cw, const float* __restrict__ cb,
                  float* __restrict__ out)
{
    __shared__ float lt[128][33];
    __shared__ float cws[32][26];
    __shared__ float red[128][26];

    const int tid = threadIdx.x;
    const int row = tid & 127;
    const int kh = tid >> 7;
    const int row0 = blockIdx.x * 128;

    float acc[OUTC];
#pragma unroll
    for (int o = 0; o < OUTC; o++) acc[o] = 0.f;

    for (int kt = 0; kt < PP / 32; kt++) {
#pragma unroll
        for (int i = 0; i < 16; i++) {
            int flat = i * 256 + tid;
            int r = flat >> 5, k = flat & 31;
            lt[r][k] = g_logits[(size_t)(row0 + r) * PP + kt * 32 + k];
        }
#pragma unroll
        for (int i = 0; i < 4; i++) {
            int flat = i * 256 + tid;
            if (flat < 32 * OUTC) {
                int k = flat / OUTC, o = flat % OUTC;
                cws[k][o] = cw[(size_t)o * PP + kt * 32 + k];
            }
        }
        __syncthreads();
#pragma unroll
        for (int kk = 0; kk < 16; kk++) {
            int k = kh * 16 + kk;
            float v = lt[row][k];
#pragma unroll
            for (int o = 0; o < OUTC; o++)
                acc[o] = fmaf(v, cws[k][o], acc[o]);
        }
        __syncthreads();
    }

    if (kh == 1) {
#pragma unroll
        for (int o = 0; o < OUTC; o++) red[row][o] = acc[o];
    }
    __syncthreads();
    if (kh == 0) {
#pragma unroll
        for (int o = 0; o < OUTC; o++)
            out[(size_t)(row0 + row) * OUTC + o] = acc[o] + red[row][o] + cb[o];
    }
}

// =================================================================
// launch
// =================================================================
extern "C" void kernel_launch(void* const* d_in, const int* in_sizes, int n_in,
                              void* d_out, int out_size)
{
    const float* patient    = (const float*)d_in[0];
    const float* protos     = (const float*)d_in[1];
    const int*   index      = (const int*)  d_in[2];
    const float* bilinear_w = (const float*)d_in[3];
    const float* bilinear_b = (const float*)d_in[4];
    const float* lin_w      = (const float*)d_in[5];
    const float* proto_fc_w = (const float*)d_in[6];
    const float* proto_fc_b = (const float*)d_in[7];
    const float* class_fc_w = (const float*)d_in[8];
    const float* class_fc_b = (const float*)d_in[9];
    float* out = (float*)d_out;

    float *pPW, *pPsq, *pLogits;
    float4* pTop2;
    __half *pPaHi, *pPrHi, *pPrLo, *pFcHi, *pWtHi, *pWtLo, *pMxHi;
    cudaGetSymbolAddress((void**)&pPW, g_PW);
    cudaGetSymbolAddress((void**)&pPsq, g_psq);
    cudaGetSymbolAddress((void**)&pLogits, g_logits);
    cudaGetSymbolAddress((void**)&pTop2, g_top2);
    cudaGetSymbolAddress((void**)&pPaHi, g_pa_hi);
    cudaGetSymbolAddress((void**)&pPrHi, g_pr_hi);
    cudaGetSymbolAddress((void**)&pPrLo, g_pr_lo);
    cudaGetSymbolAddress((void**)&pFcHi, g_fc_hi);
    cudaGetSymbolAddress((void**)&pWtHi, g_wt_hi);
    cudaGetSymbolAddress((void**)&pWtLo, g_wt_lo);
    cudaGetSymbolAddress((void**)&pMxHi, g_mx_hi);

    const int SM1 = 4 * 2 * 8192 + 4096;   // 69632  (PASSES=1, NST=4)
    const int SM3 = 3 * 4 * 8192 + 4096;   // 102400 (PASSES=3, NST=3)
    cudaFuncSetAttribute(hmma_gemm_kernel<1,0,4>, cudaFuncAttributeMaxDynamicSharedMemorySize, SM1);
    cudaFuncSetAttribute(hmma_gemm_kernel<1,1,4>, cudaFuncAttributeMaxDynamicSharedMemorySize, SM1);
    cudaFuncSetAttribute(hmma_gemm_kernel<3,2,3>, cudaFuncAttributeMaxDynamicSharedMemorySize, SM3);

    prep_kernel<<<PP, 256>>>(protos, lin_w);

    convert_kernel<<<(BB * DD / 4) / 256, 256>>>(patient, pPaHi, BB * DD / 4);
    split_kernel<<<(PP * DD / 4) / 256, 256>>>(protos, pPrHi, pPrLo, PP * DD / 4);
    convert_kernel<<<(PP * DD / 4) / 256, 256>>>(proto_fc_w, pFcHi, PP * DD / 4);
    splitT_kernel<<<dim3(32, 32), 256>>>(bilinear_w, pWtHi, pWtLo);

    // PW = protos @ W  (3-pass: lam path stays accurate)
    hmma_gemm_kernel<3,2,3><<<dim3(DD / 128, PP / 128), 256, SM3>>>(
        pPrHi, pPrLo, pWtHi, pWtLo, nullptr, pPW);

    // distance GEMM (1-pass fp16, deep pipeline) + per-warp top2 candidates
    hmma_gemm_kernel<1,0,4><<<dim3(PP / 128, BB / 128), 256, SM1>>>(
        pPaHi, nullptr, pPrHi, nullptr, pPsq, (float*)pTop2);

    argmin_reduce_kernel<<<BB / 8, 256>>>(patient, protos);

    lam_kernel<<<BB / 8, 256>>>(index, bilinear_b, protos);

    mix_kernel<<<BB, 256>>>(patient, index);

    // logits GEMM (1-pass fp16, deep pipeline; +bias, leaky)
    hmma_gemm_kernel<1,1,4><<<dim3(PP / 128, BB / 128), 256, SM1>>>(
        pMxHi, nullptr, pFcHi, nullptr, proto_fc_b, pLogits);

    class_kernel<<<BB / 128, 256>>>(class_fc_w, class_fc_b, out);
}